// round 5
// baseline (speedup 1.0000x reference)
#include <cuda_runtime.h>
#include <math.h>

// ---------------------------------------------------------------------------
// MoE forward, gate-then-dispatch (sparse top-4 of 16 experts).
// Pipeline:
//   concat -> gate GEMM1 -> LN+GELU -> gate GEMM2 + softmax + top4 + renorm
//   -> count/scan/scatter dispatch -> expert GEMM1 (gathered A, BN+GELU epi)
//   -> expert GEMM2 (scattered C, BN+GELU epi) -> weighted combine
//   -> final GEMM1 (BN+GELU) -> final small GEMM -> out [4096,20] fp32
// All scratch is __device__ globals (no allocation). All launches on the
// default stream, graph-capturable (no syncs, no mallocs, no memcpys).
// ---------------------------------------------------------------------------

#define BTOK 4096
#define DIN  512
#define HDIM 1024
#define NEXP 16
#define KSEL 4
#define NCLS 20
#define EPSN 1e-5f

// -------------------------- device scratch --------------------------------
__device__ float g_combined[BTOK * DIN];          // 8 MB
__device__ float g_g1[BTOK * HDIM];               // 16 MB (gate hidden)
__device__ int   g_tidx[BTOK * KSEL];
__device__ float g_tw[BTOK * KSEL];
__device__ int   g_counts[NEXP];
__device__ int   g_cursor[NEXP];
__device__ int   g_offsets[NEXP + 1];
__device__ int   g_rowinfo[BTOK * KSEL];          // dispatched row -> b*4+k
__device__ float g_h1[BTOK * KSEL * HDIM];        // 64 MB
__device__ float g_h2[BTOK * KSEL * HDIM];        // 64 MB, indexed by b*4+k
__device__ float g_fused[BTOK * HDIM];            // 16 MB
__device__ float g_o1[BTOK * 512];                // 8 MB

__device__ __forceinline__ float gelu_f(float x) {
    return 0.5f * x * (1.0f + erff(x * 0.70710678118654752440f));
}

// -------------------------- concat ----------------------------------------
__global__ void concat_kernel(const float* __restrict__ wifi,
                              const float* __restrict__ rfid,
                              float* __restrict__ comb) {
    int i = blockIdx.x * 256 + threadIdx.x;
    if (i < BTOK * DIN) {
        int b = i >> 9;       // / 512
        int c = i & 511;
        comb[i] = (c < 256) ? wifi[b * 256 + c] : rfid[b * 256 + (c - 256)];
    }
}

// -------------------------- tiled SGEMM -----------------------------------
// 128x128 tile, BK=16, 256 threads, 8x8 per-thread microtile.
// SEG:     blockIdx.z selects expert segment via g_offsets; weights/params
//          advance by e*K*N / e*N.
// GATHER:  A row index = rowinfo[globalRow] >> 2 (token id).
// SCATTER: C row index = rowinfo[globalRow] (b*4+k slot).
// BN:      epilogue does bias + BatchNorm(eval) + exact GELU; otherwise
//          bias only (raw pre-activation stored).
template<bool SEG, bool GATHER, bool SCATTER, bool BN>
__global__ void __launch_bounds__(256, 2) gemm_ep(
    const float* __restrict__ A, const float* __restrict__ Bw,
    float* __restrict__ C,
    int Mfixed, int N, int K,
    const int* __restrict__ offsets, const int* __restrict__ rowinfo,
    const float* __restrict__ bias,
    const float* __restrict__ bng, const float* __restrict__ bnb,
    const float* __restrict__ bnm, const float* __restrict__ bnv)
{
    int m0 = 0, M = Mfixed;
    if (SEG) {
        int e = blockIdx.z;
        m0 = offsets[e];
        M  = offsets[e + 1] - m0;
        Bw   += (size_t)e * K * N;
        bias += (size_t)e * N;
        if (BN) {
            bng += (size_t)e * N; bnb += (size_t)e * N;
            bnm += (size_t)e * N; bnv += (size_t)e * N;
        }
    }
    const int mtile = blockIdx.x * 128;
    if (mtile >= M) return;
    const int ntile = blockIdx.y * 128;

    __shared__ float As[16][128];
    __shared__ float Bs[16][128];

    const int tid = threadIdx.x;
    const int tx = tid & 15, ty = tid >> 4;

    // A tile load mapping (two rows per thread, one float4 each)
    const int arow0 = tid >> 2;
    const int arow1 = arow0 + 64;
    const int ak4   = (tid & 3) << 2;
    const bool r0ok = (mtile + arow0) < M;
    const bool r1ok = (mtile + arow1) < M;
    size_t ab0 = 0, ab1 = 0;
    if (r0ok) { int gr = m0 + mtile + arow0; ab0 = (size_t)(GATHER ? (rowinfo[gr] >> 2) : gr) * K; }
    if (r1ok) { int gr = m0 + mtile + arow1; ab1 = (size_t)(GATHER ? (rowinfo[gr] >> 2) : gr) * K; }

    // B tile load mapping (two rows per thread, one float4 each)
    const int brow = tid >> 5;
    const int bc4  = (tid & 31) << 2;

    float acc[8][8];
#pragma unroll
    for (int i = 0; i < 8; i++)
#pragma unroll
        for (int j = 0; j < 8; j++) acc[i][j] = 0.0f;

    for (int kt = 0; kt < K; kt += 16) {
        float4 a0 = make_float4(0.f, 0.f, 0.f, 0.f);
        float4 a1 = make_float4(0.f, 0.f, 0.f, 0.f);
        if (r0ok) a0 = *(const float4*)(A + ab0 + kt + ak4);
        if (r1ok) a1 = *(const float4*)(A + ab1 + kt + ak4);
        As[ak4 + 0][arow0] = a0.x; As[ak4 + 1][arow0] = a0.y;
        As[ak4 + 2][arow0] = a0.z; As[ak4 + 3][arow0] = a0.w;
        As[ak4 + 0][arow1] = a1.x; As[ak4 + 1][arow1] = a1.y;
        As[ak4 + 2][arow1] = a1.z; As[ak4 + 3][arow1] = a1.w;
        *(float4*)&Bs[brow    ][bc4] = *(const float4*)(Bw + (size_t)(kt + brow    ) * N + ntile + bc4);
        *(float4*)&Bs[brow + 8][bc4] = *(const float4*)(Bw + (size_t)(kt + brow + 8) * N + ntile + bc4);
        __syncthreads();
#pragma unroll
        for (int k = 0; k < 16; k++) {
            float af[8], bf[8];
            *(float4*)&af[0] = *(float4*)&As[k][ty * 8];
            *(float4*)&af[4] = *(float4*)&As[k][ty * 8 + 4];
            *(float4*)&bf[0] = *(float4*)&Bs[k][tx * 8];
            *(float4*)&bf[4] = *(float4*)&Bs[k][tx * 8 + 4];
#pragma unroll
            for (int i = 0; i < 8; i++)
#pragma unroll
                for (int j = 0; j < 8; j++)
                    acc[i][j] += af[i] * bf[j];
        }
        __syncthreads();
    }

    const int cn = ntile + tx * 8;
    float bi[8], sc[8], sh[8];
    *(float4*)&bi[0] = *(const float4*)(bias + cn);
    *(float4*)&bi[4] = *(const float4*)(bias + cn + 4);
    if (BN) {
#pragma unroll
        for (int j = 0; j < 8; j++) {
            float gv = bng[cn + j], bv = bnb[cn + j];
            float mv = bnm[cn + j], vv = bnv[cn + j];
            sc[j] = gv * rsqrtf(vv + EPSN);
            sh[j] = bv - mv * sc[j];
        }
    }
#pragma unroll
    for (int i = 0; i < 8; i++) {
        int rl = mtile + ty * 8 + i;
        if (rl < M) {
            int gr = m0 + rl;
            int crow = SCATTER ? rowinfo[gr] : gr;
            float v[8];
#pragma unroll
            for (int j = 0; j < 8; j++) {
                float z = acc[i][j] + bi[j];
                if (BN) z = gelu_f(z * sc[j] + sh[j]);
                v[j] = z;
            }
            float* cp = C + (size_t)crow * N + cn;
            *(float4*)cp       = *(float4*)&v[0];
            *(float4*)(cp + 4) = *(float4*)&v[4];
        }
    }
}

// -------------------------- LayerNorm + GELU (in place) -------------------
__global__ void ln_gelu_kernel(float* __restrict__ x,
                               const float* __restrict__ g,
                               const float* __restrict__ b) {
    int row = blockIdx.x;
    float* xr = x + (size_t)row * HDIM;
    int t = threadIdx.x;  // 256 threads, 4 elems each
    float4 v = *(float4*)&xr[t * 4];
    float s = v.x + v.y + v.z + v.w;
    float q = v.x * v.x + v.y * v.y + v.z * v.z + v.w * v.w;
#pragma unroll
    for (int o = 16; o; o >>= 1) {
        s += __shfl_down_sync(0xffffffffu, s, o);
        q += __shfl_down_sync(0xffffffffu, q, o);
    }
    __shared__ float ss[8], qq[8];
    int w = t >> 5, l = t & 31;
    if (l == 0) { ss[w] = s; qq[w] = q; }
    __syncthreads();
    if (w == 0) {
        s = (l < 8) ? ss[l] : 0.0f;
        q = (l < 8) ? qq[l] : 0.0f;
#pragma unroll
        for (int o = 4; o; o >>= 1) {
            s += __shfl_down_sync(0xffffffffu, s, o);
            q += __shfl_down_sync(0xffffffffu, q, o);
        }
        if (l == 0) { ss[0] = s; qq[0] = q; }
    }
    __syncthreads();
    float mu  = ss[0] * (1.0f / HDIM);
    float var = qq[0] * (1.0f / HDIM) - mu * mu;
    float r = rsqrtf(var + EPSN);
    float4 gv = *(const float4*)&g[t * 4];
    float4 bv = *(const float4*)&b[t * 4];
    v.x = gelu_f((v.x - mu) * r * gv.x + bv.x);
    v.y = gelu_f((v.y - mu) * r * gv.y + bv.y);
    v.z = gelu_f((v.z - mu) * r * gv.z + bv.z);
    v.w = gelu_f((v.w - mu) * r * gv.w + bv.w);
    *(float4*)&xr[t * 4] = v;
}

// -------------------------- gate logits + softmax + top4 ------------------
__global__ void gate_topk_kernel(const float* __restrict__ g1,
                                 const float* __restrict__ w2,
                                 const float* __restrict__ b2,
                                 int* __restrict__ tidx,
                                 float* __restrict__ tw,
                                 int* __restrict__ counts) {
    int b = blockIdx.x;
    int t = threadIdx.x;           // 128 = 16 experts x 8 lanes
    int e = t >> 3, sub = t & 7;
    const float* row = g1 + (size_t)b * HDIM;
    float s = 0.0f;
    for (int k = sub; k < HDIM; k += 8)
        s += row[k] * w2[k * NEXP + e];
    s += __shfl_down_sync(0xffffffffu, s, 4);
    s += __shfl_down_sync(0xffffffffu, s, 2);
    s += __shfl_down_sync(0xffffffffu, s, 1);
    __shared__ float logit[NEXP];
    if (sub == 0) logit[e] = s + b2[e];
    __syncthreads();
    if (t == 0) {
        float mx = -1e30f;
        for (int i = 0; i < NEXP; i++) mx = fmaxf(mx, logit[i]);
        float p[NEXP], sum = 0.0f;
        for (int i = 0; i < NEXP; i++) { p[i] = expf(logit[i] - mx); sum += p[i]; }
        float inv = 1.0f / sum;
        // top-4 of softmax probs (sorted desc, lowest-index tie-break)
        bool used[NEXP];
        for (int i = 0; i < NEXP; i++) used[i] = false;
        int idx[KSEL]; float val[KSEL];
        for (int tk = 0; tk < KSEL; tk++) {
            int best = -1; float bv = -1e30f;
            for (int i = 0; i < NEXP; i++)
                if (!used[i] && p[i] > bv) { bv = p[i]; best = i; }
            used[best] = true;
            idx[tk] = best;
            val[tk] = bv * inv;
        }
        // softmax over the 4 selected gate values
        float m2 = val[0];  // largest
        float e2[KSEL], s2 = 0.0f;
        for (int tk = 0; tk < KSEL; tk++) { e2[tk] = expf(val[tk] - m2); s2 += e2[tk]; }
        float inv2 = 1.0f / s2;
        for (int tk = 0; tk < KSEL; tk++) {
            tidx[b * KSEL + tk] = idx[tk];
            tw[b * KSEL + tk]   = e2[tk] * inv2;
            atomicAdd(&counts[idx[tk]], 1);
        }
    }
}

// -------------------------- dispatch bookkeeping --------------------------
__global__ void reset_kernel(int* __restrict__ counts) {
    if (threadIdx.x < NEXP) counts[threadIdx.x] = 0;
}

__global__ void scan_kernel(const int* __restrict__ counts,
                            int* __restrict__ offsets,
                            int* __restrict__ cursor) {
    if (threadIdx.x == 0) {
        int acc = 0;
        for (int e = 0; e < NEXP; e++) {
            offsets[e] = acc;
            cursor[e]  = acc;
            acc += counts[e];
        }
        offsets[NEXP] = acc;
    }
}

__global__ void scatter_kernel(const int* __restrict__ tidx,
                               int* __restrict__ cursor,
                               int* __restrict__ rowinfo) {
    int i = blockIdx.x * 256 + threadIdx.x;  // i = b*4+k
    if (i < BTOK * KSEL) {
        int e = tidx[i];
        int pos = atomicAdd(&cursor[e], 1);
        rowinfo[pos] = i;
    }
}

// -------------------------- weighted top-k combine ------------------------
__global__ void combine_kernel(const float* __restrict__ h2,
                               const float* __restrict__ tw,
                               float* __restrict__ fused) {
    int idx = blockIdx.x * 256 + threadIdx.x;
    if (idx < BTOK * HDIM) {
        int b = idx >> 10;
        int h = idx & (HDIM - 1);
        const float* base = h2 + ((size_t)b * KSEL) * HDIM + h;
        const float* w = tw + b * KSEL;
        fused[idx] = w[0] * base[0]
                   + w[1] * base[HDIM]
                   + w[2] * base[2 * HDIM]
                   + w[3] * base[3 * HDIM];
    }
}

// -------------------------- final small GEMM [4096,512]x[512,20] ----------
__global__ void final_kernel(const float* __restrict__ o1,
                             const float* __restrict__ w2,
                             const float* __restrict__ b2,
                             float* __restrict__ out) {
    int b = blockIdx.x;
    __shared__ float row[512];
    int t = threadIdx.x;  // 160 = 20 cols x 8 lanes
    for (int k = t; k < 512; k += 160) row[k] = o1[(size_t)b * 512 + k];
    __syncthreads();
    int c = t >> 3, sub = t & 7;
    float s = 0.0f;
    for (int k = sub; k < 512; k += 8)
        s += row[k] * w2[k * NCLS + c];
    s += __shfl_down_sync(0xffffffffu, s, 4);
    s += __shfl_down_sync(0xffffffffu, s, 2);
    s += __shfl_down_sync(0xffffffffu, s, 1);
    if (sub == 0) out[b * NCLS + c] = s + b2[c];
}

// -------------------------- launch ----------------------------------------
extern "C" void kernel_launch(void* const* d_in, const int* in_sizes, int n_in,
                              void* d_out, int out_size) {
    const float* wifi      = (const float*)d_in[0];
    const float* rfid      = (const float*)d_in[1];
    const float* gate_w1   = (const float*)d_in[2];
    const float* gate_b1   = (const float*)d_in[3];
    const float* gate_ln_g = (const float*)d_in[4];
    const float* gate_ln_b = (const float*)d_in[5];
    const float* gate_w2   = (const float*)d_in[6];
    const float* gate_b2   = (const float*)d_in[7];
    const float* exp_w1    = (const float*)d_in[8];
    const float* exp_b1    = (const float*)d_in[9];
    const float* exp_bn1_g = (const float*)d_in[10];
    const float* exp_bn1_b = (const float*)d_in[11];
    const float* exp_bn1_m = (const float*)d_in[12];
    const float* exp_bn1_v = (const float*)d_in[13];
    const float* exp_w2    = (const float*)d_in[14];
    const float* exp_b2    = (const float*)d_in[15];
    const float* exp_bn2_g = (const float*)d_in[16];
    const float* exp_bn2_b = (const float*)d_in[17];
    const float* exp_bn2_m = (const float*)d_in[18];
    const float* exp_bn2_v = (const float*)d_in[19];
    const float* fin_w1    = (const float*)d_in[20];
    const float* fin_b1    = (const float*)d_in[21];
    const float* fin_bn_g  = (const float*)d_in[22];
    const float* fin_bn_b  = (const float*)d_in[23];
    const float* fin_bn_m  = (const float*)d_in[24];
    const float* fin_bn_v  = (const float*)d_in[25];
    const float* fin_w2    = (const float*)d_in[26];
    const float* fin_b2    = (const float*)d_in[27];
    float* out = (float*)d_out;

    float *combined, *g1, *tw, *h1, *h2, *fused, *o1;
    int *tidx, *counts, *cursor, *offsets, *rowinfo;
    cudaGetSymbolAddress((void**)&combined, g_combined);
    cudaGetSymbolAddress((void**)&g1,       g_g1);
    cudaGetSymbolAddress((void**)&tidx,     g_tidx);
    cudaGetSymbolAddress((void**)&tw,       g_tw);
    cudaGetSymbolAddress((void**)&counts,   g_counts);
    cudaGetSymbolAddress((void**)&cursor,   g_cursor);
    cudaGetSymbolAddress((void**)&offsets,  g_offsets);
    cudaGetSymbolAddress((void**)&rowinfo,  g_rowinfo);
    cudaGetSymbolAddress((void**)&h1,       g_h1);
    cudaGetSymbolAddress((void**)&h2,       g_h2);
    cudaGetSymbolAddress((void**)&fused,    g_fused);
    cudaGetSymbolAddress((void**)&o1,       g_o1);

    // 1. concat wifi|rfid -> combined [4096,512]
    concat_kernel<<<(BTOK * DIN + 255) / 256, 256>>>(wifi, rfid, combined);

    // 2. gate GEMM1: combined @ gate_w1 + b1 -> g1 (raw, LN later)
    gemm_ep<false, false, false, false><<<dim3(32, 8, 1), 256>>>(
        combined, gate_w1, g1, BTOK, HDIM, DIN,
        nullptr, nullptr, gate_b1, nullptr, nullptr, nullptr, nullptr);

    // 3. LayerNorm + GELU in place on g1
    ln_gelu_kernel<<<BTOK, 256>>>(g1, gate_ln_g, gate_ln_b);

    // 4. gate logits + softmax + top4 + renorm; counts per expert
    reset_kernel<<<1, 32>>>(counts);
    gate_topk_kernel<<<BTOK, 128>>>(g1, gate_w2, gate_b2, tidx, tw, counts);

    // 5. dispatch: scan + scatter
    scan_kernel<<<1, 1>>>(counts, offsets, cursor);
    scatter_kernel<<<(BTOK * KSEL + 255) / 256, 256>>>(tidx, cursor, rowinfo);

    // 6. expert GEMM1: gathered combined rows @ exp_w1[e], BN1+GELU -> h1
    gemm_ep<true, true, false, true><<<dim3(32, 8, NEXP), 256>>>(
        combined, exp_w1, h1, 0, HDIM, DIN,
        offsets, rowinfo, exp_b1, exp_bn1_g, exp_bn1_b, exp_bn1_m, exp_bn1_v);

    // 7. expert GEMM2: h1 @ exp_w2[e], BN2+GELU -> h2 (scattered to b*4+k)
    gemm_ep<true, false, true, true><<<dim3(32, 8, NEXP), 256>>>(
        h1, exp_w2, h2, 0, HDIM, HDIM,
        offsets, rowinfo, exp_b2, exp_bn2_g, exp_bn2_b, exp_bn2_m, exp_bn2_v);

    // 8. weighted combine over top-4 -> fused [4096,1024]
    combine_kernel<<<(BTOK * HDIM + 255) / 256, 256>>>(h2, tw, fused);

    // 9. final GEMM1: fused @ fin_w1, BN+GELU -> o1 [4096,512]
    gemm_ep<false, false, false, true><<<dim3(32, 4, 1), 256>>>(
        fused, fin_w1, o1, BTOK, 512, HDIM,
        nullptr, nullptr, fin_b1, fin_bn_g, fin_bn_b, fin_bn_m, fin_bn_v);

    // 10. final head: o1 @ fin_w2 + b2 -> out [4096,20]
    final_kernel<<<BTOK, 160>>>(o1, fin_w2, fin_b2, out);
}

// round 6
// speedup vs baseline: 1.0018x; 1.0018x over previous
#include <cuda_runtime.h>
#include <math.h>

// ---------------------------------------------------------------------------
// MoE forward, gate-then-dispatch (sparse top-4 of 16 experts).
// Pipeline:
//   concat -> gate GEMM1 -> LN+GELU -> gate GEMM2 + softmax + top4 + renorm
//   -> count/scan/scatter dispatch -> expert GEMM1 (gathered A, BN+GELU epi)
//   -> expert GEMM2 (scattered C, BN+GELU epi) -> weighted combine
//   -> final GEMM1 (BN+GELU) -> final small GEMM -> out [4096,20] fp32
// All scratch is __device__ globals (no allocation). All launches on the
// default stream, graph-capturable (no syncs, no mallocs, no memcpys).
// ---------------------------------------------------------------------------

#define BTOK 4096
#define DIN  512
#define HDIM 1024
#define NEXP 16
#define KSEL 4
#define NCLS 20
#define EPSN 1e-5f

// -------------------------- device scratch --------------------------------
__device__ float g_combined[BTOK * DIN];          // 8 MB
__device__ float g_g1[BTOK * HDIM];               // 16 MB (gate hidden)
__device__ int   g_tidx[BTOK * KSEL];
__device__ float g_tw[BTOK * KSEL];
__device__ int   g_counts[NEXP];
__device__ int   g_cursor[NEXP];
__device__ int   g_offsets[NEXP + 1];
__device__ int   g_rowinfo[BTOK * KSEL];          // dispatched row -> b*4+k
__device__ float g_h1[BTOK * KSEL * HDIM];        // 64 MB
__device__ float g_h2[BTOK * KSEL * HDIM];        // 64 MB, indexed by b*4+k
__device__ float g_fused[BTOK * HDIM];            // 16 MB
__device__ float g_o1[BTOK * 512];                // 8 MB

__device__ __forceinline__ float gelu_f(float x) {
    return 0.5f * x * (1.0f + erff(x * 0.70710678118654752440f));
}

// -------------------------- concat ----------------------------------------
__global__ void concat_kernel(const float* __restrict__ wifi,
                              const float* __restrict__ rfid,
                              float* __restrict__ comb) {
    int i = blockIdx.x * 256 + threadIdx.x;
    if (i < BTOK * DIN) {
        int b = i >> 9;       // / 512
        int c = i & 511;
        comb[i] = (c < 256) ? wifi[b * 256 + c] : rfid[b * 256 + (c - 256)];
    }
}

// -------------------------- tiled SGEMM -----------------------------------
// 128x128 tile, BK=16, 256 threads, 8x8 per-thread microtile.
// SEG:     blockIdx.z selects expert segment via g_offsets; weights/params
//          advance by e*K*N / e*N.
// GATHER:  A row index = rowinfo[globalRow] >> 2 (token id).
// SCATTER: C row index = rowinfo[globalRow] (b*4+k slot).
// BN:      epilogue does bias + BatchNorm(eval) + exact GELU; otherwise
//          bias only (raw pre-activation stored).
template<bool SEG, bool GATHER, bool SCATTER, bool BN>
__global__ void __launch_bounds__(256, 2) gemm_ep(
    const float* __restrict__ A, const float* __restrict__ Bw,
    float* __restrict__ C,
    int Mfixed, int N, int K,
    const int* __restrict__ offsets, const int* __restrict__ rowinfo,
    const float* __restrict__ bias,
    const float* __restrict__ bng, const float* __restrict__ bnb,
    const float* __restrict__ bnm, const float* __restrict__ bnv)
{
    int m0 = 0, M = Mfixed;
    if (SEG) {
        int e = blockIdx.z;
        m0 = offsets[e];
        M  = offsets[e + 1] - m0;
        Bw   += (size_t)e * K * N;
        bias += (size_t)e * N;
        if (BN) {
            bng += (size_t)e * N; bnb += (size_t)e * N;
            bnm += (size_t)e * N; bnv += (size_t)e * N;
        }
    }
    const int mtile = blockIdx.x * 128;
    if (mtile >= M) return;
    const int ntile = blockIdx.y * 128;

    __shared__ float As[16][128];
    __shared__ float Bs[16][128];

    const int tid = threadIdx.x;
    const int tx = tid & 15, ty = tid >> 4;

    // A tile load mapping (two rows per thread, one float4 each)
    const int arow0 = tid >> 2;
    const int arow1 = arow0 + 64;
    const int ak4   = (tid & 3) << 2;
    const bool r0ok = (mtile + arow0) < M;
    const bool r1ok = (mtile + arow1) < M;
    size_t ab0 = 0, ab1 = 0;
    if (r0ok) { int gr = m0 + mtile + arow0; ab0 = (size_t)(GATHER ? (rowinfo[gr] >> 2) : gr) * K; }
    if (r1ok) { int gr = m0 + mtile + arow1; ab1 = (size_t)(GATHER ? (rowinfo[gr] >> 2) : gr) * K; }

    // B tile load mapping (two rows per thread, one float4 each)
    const int brow = tid >> 5;
    const int bc4  = (tid & 31) << 2;

    float acc[8][8];
#pragma unroll
    for (int i = 0; i < 8; i++)
#pragma unroll
        for (int j = 0; j < 8; j++) acc[i][j] = 0.0f;

    for (int kt = 0; kt < K; kt += 16) {
        float4 a0 = make_float4(0.f, 0.f, 0.f, 0.f);
        float4 a1 = make_float4(0.f, 0.f, 0.f, 0.f);
        if (r0ok) a0 = *(const float4*)(A + ab0 + kt + ak4);
        if (r1ok) a1 = *(const float4*)(A + ab1 + kt + ak4);
        As[ak4 + 0][arow0] = a0.x; As[ak4 + 1][arow0] = a0.y;
        As[ak4 + 2][arow0] = a0.z; As[ak4 + 3][arow0] = a0.w;
        As[ak4 + 0][arow1] = a1.x; As[ak4 + 1][arow1] = a1.y;
        As[ak4 + 2][arow1] = a1.z; As[ak4 + 3][arow1] = a1.w;
        *(float4*)&Bs[brow    ][bc4] = *(const float4*)(Bw + (size_t)(kt + brow    ) * N + ntile + bc4);
        *(float4*)&Bs[brow + 8][bc4] = *(const float4*)(Bw + (size_t)(kt + brow + 8) * N + ntile + bc4);
        __syncthreads();
#pragma unroll
        for (int k = 0; k < 16; k++) {
            float af[8], bf[8];
            *(float4*)&af[0] = *(float4*)&As[k][ty * 8];
            *(float4*)&af[4] = *(float4*)&As[k][ty * 8 + 4];
            *(float4*)&bf[0] = *(float4*)&Bs[k][tx * 8];
            *(float4*)&bf[4] = *(float4*)&Bs[k][tx * 8 + 4];
#pragma unroll
            for (int i = 0; i < 8; i++)
#pragma unroll
                for (int j = 0; j < 8; j++)
                    acc[i][j] += af[i] * bf[j];
        }
        __syncthreads();
    }

    const int cn = ntile + tx * 8;
    float bi[8], sc[8], sh[8];
    *(float4*)&bi[0] = *(const float4*)(bias + cn);
    *(float4*)&bi[4] = *(const float4*)(bias + cn + 4);
    if (BN) {
#pragma unroll
        for (int j = 0; j < 8; j++) {
            float gv = bng[cn + j], bv = bnb[cn + j];
            float mv = bnm[cn + j], vv = bnv[cn + j];
            sc[j] = gv * rsqrtf(vv + EPSN);
            sh[j] = bv - mv * sc[j];
        }
    }
#pragma unroll
    for (int i = 0; i < 8; i++) {
        int rl = mtile + ty * 8 + i;
        if (rl < M) {
            int gr = m0 + rl;
            int crow = SCATTER ? rowinfo[gr] : gr;
            float v[8];
#pragma unroll
            for (int j = 0; j < 8; j++) {
                float z = acc[i][j] + bi[j];
                if (BN) z = gelu_f(z * sc[j] + sh[j]);
                v[j] = z;
            }
            float* cp = C + (size_t)crow * N + cn;
            *(float4*)cp       = *(float4*)&v[0];
            *(float4*)(cp + 4) = *(float4*)&v[4];
        }
    }
}

// -------------------------- LayerNorm + GELU (in place) -------------------
__global__ void ln_gelu_kernel(float* __restrict__ x,
                               const float* __restrict__ g,
                               const float* __restrict__ b) {
    int row = blockIdx.x;
    float* xr = x + (size_t)row * HDIM;
    int t = threadIdx.x;  // 256 threads, 4 elems each
    float4 v = *(float4*)&xr[t * 4];
    float s = v.x + v.y + v.z + v.w;
    float q = v.x * v.x + v.y * v.y + v.z * v.z + v.w * v.w;
#pragma unroll
    for (int o = 16; o; o >>= 1) {
        s += __shfl_down_sync(0xffffffffu, s, o);
        q += __shfl_down_sync(0xffffffffu, q, o);
    }
    __shared__ float ss[8], qq[8];
    int w = t >> 5, l = t & 31;
    if (l == 0) { ss[w] = s; qq[w] = q; }
    __syncthreads();
    if (w == 0) {
        s = (l < 8) ? ss[l] : 0.0f;
        q = (l < 8) ? qq[l] : 0.0f;
#pragma unroll
        for (int o = 4; o; o >>= 1) {
            s += __shfl_down_sync(0xffffffffu, s, o);
            q += __shfl_down_sync(0xffffffffu, q, o);
        }
        if (l == 0) { ss[0] = s; qq[0] = q; }
    }
    __syncthreads();
    float mu  = ss[0] * (1.0f / HDIM);
    float var = qq[0] * (1.0f / HDIM) - mu * mu;
    float r = rsqrtf(var + EPSN);
    float4 gv = *(const float4*)&g[t * 4];
    float4 bv = *(const float4*)&b[t * 4];
    v.x = gelu_f((v.x - mu) * r * gv.x + bv.x);
    v.y = gelu_f((v.y - mu) * r * gv.y + bv.y);
    v.z = gelu_f((v.z - mu) * r * gv.z + bv.z);
    v.w = gelu_f((v.w - mu) * r * gv.w + bv.w);
    *(float4*)&xr[t * 4] = v;
}

// -------------------------- gate logits + softmax + top4 ------------------
__global__ void gate_topk_kernel(const float* __restrict__ g1,
                                 const float* __restrict__ w2,
                                 const float* __restrict__ b2,
                                 int* __restrict__ tidx,
                                 float* __restrict__ tw,
                                 int* __restrict__ counts) {
    int b = blockIdx.x;
    int t = threadIdx.x;           // 128 = 16 experts x 8 lanes
    int e = t >> 3, sub = t & 7;
    const float* row = g1 + (size_t)b * HDIM;
    float s = 0.0f;
    for (int k = sub; k < HDIM; k += 8)
        s += row[k] * w2[k * NEXP + e];
    s += __shfl_down_sync(0xffffffffu, s, 4);
    s += __shfl_down_sync(0xffffffffu, s, 2);
    s += __shfl_down_sync(0xffffffffu, s, 1);
    __shared__ float logit[NEXP];
    if (sub == 0) logit[e] = s + b2[e];
    __syncthreads();
    if (t == 0) {
        float mx = -1e30f;
        for (int i = 0; i < NEXP; i++) mx = fmaxf(mx, logit[i]);
        float p[NEXP], sum = 0.0f;
        for (int i = 0; i < NEXP; i++) { p[i] = expf(logit[i] - mx); sum += p[i]; }
        float inv = 1.0f / sum;
        // top-4 of softmax probs (sorted desc, lowest-index tie-break)
        bool used[NEXP];
        for (int i = 0; i < NEXP; i++) used[i] = false;
        int idx[KSEL]; float val[KSEL];
        for (int tk = 0; tk < KSEL; tk++) {
            int best = -1; float bv = -1e30f;
            for (int i = 0; i < NEXP; i++)
                if (!used[i] && p[i] > bv) { bv = p[i]; best = i; }
            used[best] = true;
            idx[tk] = best;
            val[tk] = bv * inv;
        }
        // softmax over the 4 selected gate values
        float m2 = val[0];  // largest
        float e2[KSEL], s2 = 0.0f;
        for (int tk = 0; tk < KSEL; tk++) { e2[tk] = expf(val[tk] - m2); s2 += e2[tk]; }
        float inv2 = 1.0f / s2;
        for (int tk = 0; tk < KSEL; tk++) {
            tidx[b * KSEL + tk] = idx[tk];
            tw[b * KSEL + tk]   = e2[tk] * inv2;
            atomicAdd(&counts[idx[tk]], 1);
        }
    }
}

// -------------------------- dispatch bookkeeping --------------------------
__global__ void reset_kernel(int* __restrict__ counts) {
    if (threadIdx.x < NEXP) counts[threadIdx.x] = 0;
}

__global__ void scan_kernel(const int* __restrict__ counts,
                            int* __restrict__ offsets,
                            int* __restrict__ cursor) {
    if (threadIdx.x == 0) {
        int acc = 0;
        for (int e = 0; e < NEXP; e++) {
            offsets[e] = acc;
            cursor[e]  = acc;
            acc += counts[e];
        }
        offsets[NEXP] = acc;
    }
}

__global__ void scatter_kernel(const int* __restrict__ tidx,
                               int* __restrict__ cursor,
                               int* __restrict__ rowinfo) {
    int i = blockIdx.x * 256 + threadIdx.x;  // i = b*4+k
    if (i < BTOK * KSEL) {
        int e = tidx[i];
        int pos = atomicAdd(&cursor[e], 1);
        rowinfo[pos] = i;
    }
}

// -------------------------- weighted top-k combine ------------------------
__global__ void combine_kernel(const float* __restrict__ h2,
                               const float* __restrict__ tw,
                               float* __restrict__ fused) {
    int idx = blockIdx.x * 256 + threadIdx.x;
    if (idx < BTOK * HDIM) {
        int b = idx >> 10;
        int h = idx & (HDIM - 1);
        const float* base = h2 + ((size_t)b * KSEL) * HDIM + h;
        const float* w = tw + b * KSEL;
        fused[idx] = w[0] * base[0]
                   + w[1] * base[HDIM]
                   + w[2] * base[2 * HDIM]
                   + w[3] * base[3 * HDIM];
    }
}

// -------------------------- final small GEMM [4096,512]x[512,20] ----------
__global__ void final_kernel(const float* __restrict__ o1,
                             const float* __restrict__ w2,
                             const float* __restrict__ b2,
                             float* __restrict__ out) {
    int b = blockIdx.x;
    __shared__ float row[512];
    int t = threadIdx.x;  // 160 = 20 cols x 8 lanes
    for (int k = t; k < 512; k += 160) row[k] = o1[(size_t)b * 512 + k];
    __syncthreads();
    int c = t >> 3, sub = t & 7;
    float s = 0.0f;
    for (int k = sub; k < 512; k += 8)
        s += row[k] * w2[k * NCLS + c];
    s += __shfl_down_sync(0xffffffffu, s, 4);
    s += __shfl_down_sync(0xffffffffu, s, 2);
    s += __shfl_down_sync(0xffffffffu, s, 1);
    if (sub == 0) out[b * NCLS + c] = s + b2[c];
}

// -------------------------- launch ----------------------------------------
extern "C" void kernel_launch(void* const* d_in, const int* in_sizes, int n_in,
                              void* d_out, int out_size) {
    const float* wifi      = (const float*)d_in[0];
    const float* rfid      = (const float*)d_in[1];
    const float* gate_w1   = (const float*)d_in[2];
    const float* gate_b1   = (const float*)d_in[3];
    const float* gate_ln_g = (const float*)d_in[4];
    const float* gate_ln_b = (const float*)d_in[5];
    const float* gate_w2   = (const float*)d_in[6];
    const float* gate_b2   = (const float*)d_in[7];
    const float* exp_w1    = (const float*)d_in[8];
    const float* exp_b1    = (const float*)d_in[9];
    const float* exp_bn1_g = (const float*)d_in[10];
    const float* exp_bn1_b = (const float*)d_in[11];
    const float* exp_bn1_m = (const float*)d_in[12];
    const float* exp_bn1_v = (const float*)d_in[13];
    const float* exp_w2    = (const float*)d_in[14];
    const float* exp_b2    = (const float*)d_in[15];
    const float* exp_bn2_g = (const float*)d_in[16];
    const float* exp_bn2_b = (const float*)d_in[17];
    const float* exp_bn2_m = (const float*)d_in[18];
    const float* exp_bn2_v = (const float*)d_in[19];
    const float* fin_w1    = (const float*)d_in[20];
    const float* fin_b1    = (const float*)d_in[21];
    const float* fin_bn_g  = (const float*)d_in[22];
    const float* fin_bn_b  = (const float*)d_in[23];
    const float* fin_bn_m  = (const float*)d_in[24];
    const float* fin_bn_v  = (const float*)d_in[25];
    const float* fin_w2    = (const float*)d_in[26];
    const float* fin_b2    = (const float*)d_in[27];
    float* out = (float*)d_out;

    float *combined, *g1, *tw, *h1, *h2, *fused, *o1;
    int *tidx, *counts, *cursor, *offsets, *rowinfo;
    cudaGetSymbolAddress((void**)&combined, g_combined);
    cudaGetSymbolAddress((void**)&g1,       g_g1);
    cudaGetSymbolAddress((void**)&tidx,     g_tidx);
    cudaGetSymbolAddress((void**)&tw,       g_tw);
    cudaGetSymbolAddress((void**)&counts,   g_counts);
    cudaGetSymbolAddress((void**)&cursor,   g_cursor);
    cudaGetSymbolAddress((void**)&offsets,  g_offsets);
    cudaGetSymbolAddress((void**)&rowinfo,  g_rowinfo);
    cudaGetSymbolAddress((void**)&h1,       g_h1);
    cudaGetSymbolAddress((void**)&h2,       g_h2);
    cudaGetSymbolAddress((void**)&fused,    g_fused);
    cudaGetSymbolAddress((void**)&o1,       g_o1);

    // 1. concat wifi|rfid -> combined [4096,512]
    concat_kernel<<<(BTOK * DIN + 255) / 256, 256>>>(wifi, rfid, combined);

    // 2. gate GEMM1: combined @ gate_w1 + b1 -> g1 (raw, LN later)
    gemm_ep<false, false, false, false><<<dim3(32, 8, 1), 256>>>(
        combined, gate_w1, g1, BTOK, HDIM, DIN,
        nullptr, nullptr, gate_b1, nullptr, nullptr, nullptr, nullptr);

    // 3. LayerNorm + GELU in place on g1
    ln_gelu_kernel<<<BTOK, 256>>>(g1, gate_ln_g, gate_ln_b);

    // 4. gate logits + softmax + top4 + renorm; counts per expert
    reset_kernel<<<1, 32>>>(counts);
    gate_topk_kernel<<<BTOK, 128>>>(g1, gate_w2, gate_b2, tidx, tw, counts);

    // 5. dispatch: scan + scatter
    scan_kernel<<<1, 1>>>(counts, offsets, cursor);
    scatter_kernel<<<(BTOK * KSEL + 255) / 256, 256>>>(tidx, cursor, rowinfo);

    // 6. expert GEMM1: gathered combined rows @ exp_w1[e], BN1+GELU -> h1
    gemm_ep<true, true, false, true><<<dim3(32, 8, NEXP), 256>>>(
        combined, exp_w1, h1, 0, HDIM, DIN,
        offsets, rowinfo, exp_b1, exp_bn1_g, exp_bn1_b, exp_bn1_m, exp_bn1_v);

    // 7. expert GEMM2: h1 @ exp_w2[e], BN2+GELU -> h2 (scattered to b*4+k)
    gemm_ep<true, false, true, true><<<dim3(32, 8, NEXP), 256>>>(
        h1, exp_w2, h2, 0, HDIM, HDIM,
        offsets, rowinfo, exp_b2, exp_bn2_g, exp_bn2_b, exp_bn2_m, exp_bn2_v);

    // 8. weighted combine over top-4 -> fused [4096,1024]
    combine_kernel<<<(BTOK * HDIM + 255) / 256, 256>>>(h2, tw, fused);

    // 9. final GEMM1: fused @ fin_w1, BN+GELU -> o1 [4096,512]
    gemm_ep<false, false, false, true><<<dim3(32, 4, 1), 256>>>(
        fused, fin_w1, o1, BTOK, 512, HDIM,
        nullptr, nullptr, fin_b1, fin_bn_g, fin_bn_b, fin_bn_m, fin_bn_v);

    // 10. final head: o1 @ fin_w2 + b2 -> out [4096,20]
    final_kernel<<<BTOK, 160>>>(o1, fin_w2, fin_b2, out);
}

// round 8
// speedup vs baseline: 1.7008x; 1.6978x over previous
#include <cuda_runtime.h>
#include <cuda_bf16.h>
#include <math.h>
#include <stdint.h>

#define BTOK 4096
#define DIN  512
#define HDIM 1024
#define NEXP 16
#define KSEL 4
#define NCLS 20
#define EPSN 1e-5f

// ---- device scratch (no allocation allowed) ----
__device__ float g_combined[BTOK * DIN];
__device__ float g_g1[BTOK * HDIM];
__device__ int   g_tidx[BTOK * KSEL];
__device__ float g_tw[BTOK * KSEL];
__device__ int   g_counts[NEXP];
__device__ int   g_cursor[NEXP];
__device__ int   g_offsets[NEXP + 1];
__device__ int   g_rowinfo[BTOK * KSEL];
__device__ float g_h1[BTOK * KSEL * HDIM];
__device__ float g_h2[BTOK * KSEL * HDIM];
__device__ float g_fused[BTOK * HDIM];
__device__ float g_o1[BTOK * 512];
__device__ __nv_bfloat16 g_ew1h[NEXP * DIN * HDIM];
__device__ __nv_bfloat16 g_ew1l[NEXP * DIN * HDIM];
__device__ __nv_bfloat16 g_ew2h[NEXP * HDIM * HDIM];
__device__ __nv_bfloat16 g_ew2l[NEXP * HDIM * HDIM];
__device__ __nv_bfloat16 g_fw1h[HDIM * 512];
__device__ __nv_bfloat16 g_fw1l[HDIM * 512];

__device__ __forceinline__ float gelu_f(float x) {
    return 0.5f * x * (1.0f + erff(x * 0.70710678118654752440f));
}
__device__ __forceinline__ uint32_t smem_u32(const void* p) {
    uint32_t a;
    asm("{ .reg .u64 t; cvta.to.shared.u64 t, %1; cvt.u32.u64 %0, t; }" : "=r"(a) : "l"(p));
    return a;
}
__device__ __forceinline__ uint4 ldm4(uint32_t addr) {
    uint4 r;
    asm volatile("ldmatrix.sync.aligned.m8n8.x4.shared.b16 {%0,%1,%2,%3}, [%4];"
                 : "=r"(r.x), "=r"(r.y), "=r"(r.z), "=r"(r.w) : "r"(addr));
    return r;
}
__device__ __forceinline__ void mma_bf16(float* c, const uint4& a, uint32_t b0, uint32_t b1) {
    asm volatile(
        "mma.sync.aligned.m16n8k16.row.col.f32.bf16.bf16.f32 "
        "{%0,%1,%2,%3}, {%4,%5,%6,%7}, {%8,%9}, {%0,%1,%2,%3};"
        : "+f"(c[0]), "+f"(c[1]), "+f"(c[2]), "+f"(c[3])
        : "r"(a.x), "r"(a.y), "r"(a.z), "r"(a.w), "r"(b0), "r"(b1));
}
__device__ __forceinline__ uint32_t pk(__nv_bfloat16 a, __nv_bfloat16 b) {
    return (uint32_t)__bfloat16_as_ushort(a) | ((uint32_t)__bfloat16_as_ushort(b) << 16);
}

// ---- concat ----
__global__ void concat_kernel(const float* __restrict__ wifi, const float* __restrict__ rfid,
                              float* __restrict__ comb) {
    int i = blockIdx.x * 256 + threadIdx.x;
    if (i < BTOK * DIN) {
        int b = i >> 9, c = i & 511;
        comb[i] = (c < 256) ? wifi[b * 256 + c] : rfid[b * 256 + (c - 256)];
    }
}

// ---- weight transpose + bf16 hi/lo split: W[e,K,N] -> T{h,l}[e,N,K] ----
__global__ void wsplit_kernel(const float* __restrict__ W,
                              __nv_bfloat16* __restrict__ Th, __nv_bfloat16* __restrict__ Tl,
                              int K, int N) {
    __shared__ float tile[32][33];
    size_t base = (size_t)blockIdx.z * K * N;
    int k0 = blockIdx.y * 32, n0 = blockIdx.x * 32;
    int tx = threadIdx.x, ty = threadIdx.y;
#pragma unroll
    for (int i = 0; i < 32; i += 8)
        tile[ty + i][tx] = W[base + (size_t)(k0 + ty + i) * N + n0 + tx];
    __syncthreads();
#pragma unroll
    for (int i = 0; i < 32; i += 8) {
        int n = n0 + ty + i, k = k0 + tx;
        float x = tile[tx][ty + i];
        __nv_bfloat16 h = __float2bfloat16_rn(x);
        __nv_bfloat16 l = __float2bfloat16_rn(x - __bfloat162float(h));
        Th[base + (size_t)n * K + k] = h;
        Tl[base + (size_t)n * K + k] = l;
    }
}

// ---------------------------------------------------------------------------
// bf16 3-pass HMMA GEMM: C[M,N] = A[M,K] @ B[K,N]
// A fp32 row-major (hi/lo split on SMEM fill); B pre-split bf16 [N,K] planes.
// CTA: 128x128 tile, 256 threads (8 warps, 4(M) x 2(N)), k-chunk 32,
// double-buffered SMEM (80B padded rows, conflict-free ldmatrix),
// per-warp 32x64 via 2x8 m16n8k16 tiles, 3 mma per tile (AhBh+AhBl+AlBh).
// SMEM buffer layout (bytes): Ah[128][40bf16]@0, Al@10240, Bh@20480, Bl@30720.
// ---------------------------------------------------------------------------
static constexpr int WG_SMEM = 2 * 40960;

template<bool SEG, bool GATHER, bool SCATTER, bool BN>
__global__ void __launch_bounds__(256, 1) w_gemm(
    const float* __restrict__ A,
    const __nv_bfloat16* __restrict__ Bhp, const __nv_bfloat16* __restrict__ Blp,
    float* __restrict__ C, int Mfixed, int N, int K,
    const int* __restrict__ offsets, const int* __restrict__ rowinfo,
    const float* __restrict__ bias,
    const float* __restrict__ bng, const float* __restrict__ bnb,
    const float* __restrict__ bnm, const float* __restrict__ bnv)
{
    extern __shared__ __align__(16) char sm[];
    int m0 = 0, M = Mfixed;
    if (SEG) {
        int e = blockIdx.z;
        m0 = offsets[e];
        M  = offsets[e + 1] - m0;
        size_t wo = (size_t)e * K * N;
        Bhp += wo; Blp += wo;
        bias += (size_t)e * N;
        if (BN) { bng += (size_t)e * N; bnb += (size_t)e * N;
                  bnm += (size_t)e * N; bnv += (size_t)e * N; }
    }
    const int mtile = blockIdx.x * 128;
    if (mtile >= M) return;
    const int ntile = blockIdx.y * 128;

    const int tid = threadIdx.x, lane = tid & 31, wid = tid >> 5;
    const int warpM = wid & 3, warpN = wid >> 2;
    const uint32_t smBase = smem_u32(sm);

    // ---- gmem fill mappings ----
    const int acg = tid & 7;                    // A col-group (4 floats)
    const float* aPtr[4]; bool aval[4]; uint32_t aDst[4];
#pragma unroll
    for (int i = 0; i < 4; i++) {
        int row = (tid >> 3) + i * 32;
        bool v = (mtile + row) < M;
        aval[i] = v;
        int tok = 0;
        if (v) { int gr = m0 + mtile + row; tok = GATHER ? (rowinfo[gr] >> 2) : gr; }
        aPtr[i] = A + (size_t)tok * K + acg * 4;
        aDst[i] = (uint32_t)(row * 80 + acg * 8);
    }
    const __nv_bfloat16* bPtr[4]; uint32_t bDst[4];
#pragma unroll
    for (int i = 0; i < 4; i++) {
        int idx = tid + (i << 8);
        int plane = idx >> 9, f = idx & 511;
        int row = f >> 2, cg = f & 3;
        bPtr[i] = (plane ? Blp : Bhp) + (size_t)(ntile + row) * K + cg * 8;
        bDst[i] = (plane ? 30720u : 20480u) + (uint32_t)(row * 80 + cg * 16);
    }

    // ---- ldmatrix lane offsets (same quad pattern for A and B) ----
    const int qa = lane >> 3, ra = lane & 7;
    const int lrow = ((qa & 1) << 3) + ra;      // 0..15
    const int lcolB = ((qa >> 1) << 3) * 2;     // 0 or 16 bytes
    const uint32_t aFragOff = (uint32_t)((warpM * 32 + lrow) * 80) + lcolB;
    const uint32_t bFragOff = (uint32_t)((warpN * 64 + lrow) * 80) + lcolB + 20480u;

    float acc[2][8][4];
#pragma unroll
    for (int mt = 0; mt < 2; mt++)
#pragma unroll
        for (int nt = 0; nt < 8; nt++)
#pragma unroll
            for (int q = 0; q < 4; q++) acc[mt][nt][q] = 0.0f;

    const int NC = K >> 5;

    // ---- preload chunk 0 into buffer 0 ----
    {
        char* base = sm;
#pragma unroll
        for (int i = 0; i < 4; i++) {
            float4 v = aval[i] ? *(const float4*)aPtr[i] : make_float4(0.f, 0.f, 0.f, 0.f);
            __nv_bfloat16 hx = __float2bfloat16_rn(v.x), hy = __float2bfloat16_rn(v.y);
            __nv_bfloat16 hz = __float2bfloat16_rn(v.z), hw = __float2bfloat16_rn(v.w);
            *(uint2*)(base + aDst[i]) = make_uint2(pk(hx, hy), pk(hz, hw));
            *(uint2*)(base + 10240 + aDst[i]) = make_uint2(
                pk(__float2bfloat16_rn(v.x - __bfloat162float(hx)),
                   __float2bfloat16_rn(v.y - __bfloat162float(hy))),
                pk(__float2bfloat16_rn(v.z - __bfloat162float(hz)),
                   __float2bfloat16_rn(v.w - __bfloat162float(hw))));
        }
#pragma unroll
        for (int i = 0; i < 4; i++)
            *(uint4*)(base + bDst[i]) = *(const uint4*)bPtr[i];
    }
    __syncthreads();

    for (int c = 0; c < NC; c++) {
        // prefetch next chunk to regs
        float4 aR[4]; uint4 bR[4];
        const bool pf = (c + 1) < NC;
        if (pf) {
            const int kc = (c + 1) << 5;
#pragma unroll
            for (int i = 0; i < 4; i++)
                aR[i] = aval[i] ? *(const float4*)(aPtr[i] + kc) : make_float4(0.f, 0.f, 0.f, 0.f);
#pragma unroll
            for (int i = 0; i < 4; i++)
                bR[i] = *(const uint4*)(bPtr[i] + kc);
        }
        // compute on current buffer
        const uint32_t bb = smBase + (uint32_t)(c & 1) * 40960u;
#pragma unroll
        for (int ks = 0; ks < 2; ks++) {
            const uint32_t kso = ks * 32;   // 16 cols * 2B
            uint4 ah[2], al[2];
#pragma unroll
            for (int mt = 0; mt < 2; mt++) {
                uint32_t ao = bb + aFragOff + mt * 1280u + kso;
                ah[mt] = ldm4(ao);
                al[mt] = ldm4(ao + 10240u);
            }
            uint32_t bh[8][2], bl[8][2];
#pragma unroll
            for (int np = 0; np < 4; np++) {
                uint32_t bo = bb + bFragOff + np * 1280u + kso;
                uint4 h = ldm4(bo);
                uint4 l = ldm4(bo + 10240u);
                bh[2*np][0] = h.x; bh[2*np][1] = h.z;
                bh[2*np+1][0] = h.y; bh[2*np+1][1] = h.w;
                bl[2*np][0] = l.x; bl[2*np][1] = l.z;
                bl[2*np+1][0] = l.y; bl[2*np+1][1] = l.w;
            }
#pragma unroll
            for (int mt = 0; mt < 2; mt++)
#pragma unroll
                for (int nt = 0; nt < 8; nt++) {
                    mma_bf16(acc[mt][nt], ah[mt], bh[nt][0], bh[nt][1]);
                    mma_bf16(acc[mt][nt], ah[mt], bl[nt][0], bl[nt][1]);
                    mma_bf16(acc[mt][nt], al[mt], bh[nt][0], bh[nt][1]);
                }
        }
        // store prefetched chunk to other buffer
        if (pf) {
            char* base = sm + ((c + 1) & 1) * 40960;
#pragma unroll
            for (int i = 0; i < 4; i++) {
                float4 v = aR[i];
                __nv_bfloat16 hx = __float2bfloat16_rn(v.x), hy = __float2bfloat16_rn(v.y);
                __nv_bfloat16 hz = __float2bfloat16_rn(v.z), hw = __float2bfloat16_rn(v.w);
                *(uint2*)(base + aDst[i]) = make_uint2(pk(hx, hy), pk(hz, hw));
                *(uint2*)(base + 10240 + aDst[i]) = make_uint2(
                    pk(__float2bfloat16_rn(v.x - __bfloat162float(hx)),
                       __float2bfloat16_rn(v.y - __bfloat162float(hy))),
                    pk(__float2bfloat16_rn(v.z - __bfloat162float(hz)),
                       __float2bfloat16_rn(v.w - __bfloat162float(hw))));
            }
#pragma unroll
            for (int i = 0; i < 4; i++)
                *(uint4*)(base + bDst[i]) = bR[i];
        }
        __syncthreads();
    }

    // ---- epilogue: bias (+BN+GELU), direct from accumulators ----
    const int g = lane >> 2, tt = lane & 3;
#pragma unroll
    for (int mt = 0; mt < 2; mt++) {
#pragma unroll
        for (int half = 0; half < 2; half++) {
            int rl = mtile + warpM * 32 + mt * 16 + half * 8 + g;
            if (rl < M) {
                int gr = m0 + rl;
                int crow = SCATTER ? rowinfo[gr] : gr;
                float* cp = C + (size_t)crow * N;
#pragma unroll
                for (int nt = 0; nt < 8; nt++) {
                    int cn = ntile + warpN * 64 + nt * 8 + tt * 2;
                    float x0 = acc[mt][nt][half * 2 + 0] + __ldg(bias + cn);
                    float x1 = acc[mt][nt][half * 2 + 1] + __ldg(bias + cn + 1);
                    if (BN) {
                        x0 = gelu_f((x0 - __ldg(bnm + cn)) * rsqrtf(__ldg(bnv + cn) + EPSN)
                                    * __ldg(bng + cn) + __ldg(bnb + cn));
                        x1 = gelu_f((x1 - __ldg(bnm + cn + 1)) * rsqrtf(__ldg(bnv + cn + 1) + EPSN)
                                    * __ldg(bng + cn + 1) + __ldg(bnb + cn + 1));
                    }
                    *(float2*)(cp + cn) = make_float2(x0, x1);
                }
            }
        }
    }
}

// ---- fp32 gate GEMM (selection-exact): [4096,512]@[512,1024]+b ----
__global__ void __launch_bounds__(256, 2) gate_gemm(
    const float* __restrict__ A, const float* __restrict__ Bw,
    float* __restrict__ C, const float* __restrict__ bias)
{
    const int N = HDIM, K = DIN;
    const int mtile = blockIdx.x * 128, ntile = blockIdx.y * 128;
    __shared__ float As[16][128], Bs[16][128];
    const int tid = threadIdx.x, tx = tid & 15, ty = tid >> 4;
    const int arow0 = tid >> 2, arow1 = arow0 + 64, ak4 = (tid & 3) << 2;
    const size_t ab0 = (size_t)(mtile + arow0) * K, ab1 = (size_t)(mtile + arow1) * K;
    const int brow = tid >> 5, bc4 = (tid & 31) << 2;
    float acc[8][8];
#pragma unroll
    for (int i = 0; i < 8; i++)
#pragma unroll
        for (int j = 0; j < 8; j++) acc[i][j] = 0.0f;
    for (int kt = 0; kt < K; kt += 16) {
        float4 a0 = *(const float4*)(A + ab0 + kt + ak4);
        float4 a1 = *(const float4*)(A + ab1 + kt + ak4);
        As[ak4 + 0][arow0] = a0.x; As[ak4 + 1][arow0] = a0.y;
        As[ak4 + 2][arow0] = a0.z; As[ak4 + 3][arow0] = a0.w;
        As[ak4 + 0][arow1] = a1.x; As[ak4 + 1][arow1] = a1.y;
        As[ak4 + 2][arow1] = a1.z; As[ak4 + 3][arow1] = a1.w;
        *(float4*)&Bs[brow    ][bc4] = *(const float4*)(Bw + (size_t)(kt + brow    ) * N + ntile + bc4);
        *(float4*)&Bs[brow + 8][bc4] = *(const float4*)(Bw + (size_t)(kt + brow + 8) * N + ntile + bc4);
        __syncthreads();
#pragma unroll
        for (int k = 0; k < 16; k++) {
            float af[8], bf[8];
            *(float4*)&af[0] = *(float4*)&As[k][ty * 8];
            *(float4*)&af[4] = *(float4*)&As[k][ty * 8 + 4];
            *(float4*)&bf[0] = *(float4*)&Bs[k][tx * 8];
            *(float4*)&bf[4] = *(float4*)&Bs[k][tx * 8 + 4];
#pragma unroll
            for (int i = 0; i < 8; i++)
#pragma unroll
                for (int j = 0; j < 8; j++) acc[i][j] += af[i] * bf[j];
        }
        __syncthreads();
    }
    const int cn = ntile + tx * 8;
    float bi[8];
    *(float4*)&bi[0] = *(const float4*)(bias + cn);
    *(float4*)&bi[4] = *(const float4*)(bias + cn + 4);
#pragma unroll
    for (int i = 0; i < 8; i++) {
        float v[8];
#pragma unroll
        for (int j = 0; j < 8; j++) v[j] = acc[i][j] + bi[j];
        float* cp = C + (size_t)(mtile + ty * 8 + i) * N + cn;
        *(float4*)cp = *(float4*)&v[0];
        *(float4*)(cp + 4) = *(float4*)&v[4];
    }
}

// ---- LayerNorm + GELU (in place, row=1024) ----
__global__ void ln_gelu_kernel(float* __restrict__ x, const float* __restrict__ g,
                               const float* __restrict__ b) {
    int row = blockIdx.x;
    float* xr = x + (size_t)row * HDIM;
    int t = threadIdx.x;
    float4 v = *(float4*)&xr[t * 4];
    float s = v.x + v.y + v.z + v.w;
    float q = v.x * v.x + v.y * v.y + v.z * v.z + v.w * v.w;
#pragma unroll
    for (int o = 16; o; o >>= 1) {
        s += __shfl_down_sync(0xffffffffu, s, o);
        q += __shfl_down_sync(0xffffffffu, q, o);
    }
    __shared__ float ss[8], qq[8];
    int w = t >> 5, l = t & 31;
    if (l == 0) { ss[w] = s; qq[w] = q; }
    __syncthreads();
    if (w == 0) {
        s = (l < 8) ? ss[l] : 0.0f;
        q = (l < 8) ? qq[l] : 0.0f;
#pragma unroll
        for (int o = 4; o; o >>= 1) {
            s += __shfl_down_sync(0xffffffffu, s, o);
            q += __shfl_down_sync(0xffffffffu, q, o);
        }
        if (l == 0) { ss[0] = s; qq[0] = q; }
    }
    __syncthreads();
    float mu  = ss[0] * (1.0f / HDIM);
    float var = qq[0] * (1.0f / HDIM) - mu * mu;
    float r = rsqrtf(var + EPSN);
    float4 gv = *(const float4*)&g[t * 4];
    float4 bv = *(const float4*)&b[t * 4];
    v.x = gelu_f((v.x - mu) * r * gv.x + bv.x);
    v.y = gelu_f((v.y - mu) * r * gv.y + bv.y);
    v.z = gelu_f((v.z - mu) * r * gv.z + bv.z);
    v.w = gelu_f((v.w - mu) * r * gv.w + bv.w);
    *(float4*)&xr[t * 4] = v;
}

// ---- gate logits + softmax + top4 + renorm ----
__global__ void gate_topk_kernel(const float* __restrict__ g1, const float* __restrict__ w2,
                                 const float* __restrict__ b2, int* __restrict__ tidx,
                                 float* __restrict__ tw, int* __restrict__ counts) {
    int b = blockIdx.x, t = threadIdx.x;
    int e = t >> 3, sub = t & 7;
    const float* row = g1 + (size_t)b * HDIM;
    float s = 0.0f;
    for (int k = sub; k < HDIM; k += 8) s += row[k] * w2[k * NEXP + e];
    s += __shfl_down_sync(0xffffffffu, s, 4);
    s += __shfl_down_sync(0xffffffffu, s, 2);
    s += __shfl_down_sync(0xffffffffu, s, 1);
    __shared__ float logit[NEXP];
    if (sub == 0) logit[e] = s + b2[e];
    __syncthreads();
    if (t == 0) {
        float mx = -1e30f;
        for (int i = 0; i < NEXP; i++) mx = fmaxf(mx, logit[i]);
        float p[NEXP], sum = 0.0f;
        for (int i = 0; i < NEXP; i++) { p[i] = expf(logit[i] - mx); sum += p[i]; }
        float inv = 1.0f / sum;
        bool used[NEXP];
        for (int i = 0; i < NEXP; i++) used[i] = false;
        int idx[KSEL]; float val[KSEL];
        for (int tk = 0; tk < KSEL; tk++) {
            int best = -1; float bv = -1e30f;
            for (int i = 0; i < NEXP; i++)
                if (!used[i] && p[i] > bv) { bv = p[i]; best = i; }
            used[best] = true; idx[tk] = best; val[tk] = bv * inv;
        }
        float m2 = val[0], e2[KSEL], s2 = 0.0f;
        for (int tk = 0; tk < KSEL; tk++) { e2[tk] = expf(val[tk] - m2); s2 += e2[tk]; }
        float inv2 = 1.0f / s2;
        for (int tk = 0; tk < KSEL; tk++) {
            tidx[b * KSEL + tk] = idx[tk];
            tw[b * KSEL + tk]   = e2[tk] * inv2;
            atomicAdd(&counts[idx[tk]], 1);
        }
    }
}

// ---- dispatch bookkeeping ----
__global__ void reset_kernel(int* __restrict__ counts) {
    if (threadIdx.x < NEXP) counts[threadIdx.x] = 0;
}
__global__ void scan_kernel(const int* __restrict__ counts, int* __restrict__ offsets,
                            int* __restrict__ cursor) {
    if (threadIdx.x == 0) {
        int acc = 0;
        for (int e = 0; e < NEXP; e++) { offsets[e] = acc; cursor[e] = acc; acc += counts[e]; }
        offsets[NEXP] = acc;
    }
}
__global__ void scatter_kernel(const int* __restrict__ tidx, int* __restrict__ cursor,
                               int* __restrict__ rowinfo) {
    int i = blockIdx.x * 256 + threadIdx.x;
    if (i < BTOK * KSEL) {
        int pos = atomicAdd(&cursor[tidx[i]], 1);
        rowinfo[pos] = i;
    }
}

// ---- weighted top-k combine ----
__global__ void combine_kernel(const float* __restrict__ h2, const float* __restrict__ tw,
                               float* __restrict__ fused) {
    int idx = blockIdx.x * 256 + threadIdx.x;
    if (idx < BTOK * HDIM) {
        int b = idx >> 10, h = idx & (HDIM - 1);
        const float* base = h2 + ((size_t)b * KSEL) * HDIM + h;
        const float* w = tw + b * KSEL;
        fused[idx] = w[0] * base[0] + w[1] * base[HDIM]
                   + w[2] * base[2 * HDIM] + w[3] * base[3 * HDIM];
    }
}

// ---- final head GEMM [4096,512]x[512,20] ----
__global__ void final_kernel(const float* __restrict__ o1, const float* __restrict__ w2,
                             const float* __restrict__ b2, float* __restrict__ out) {
    int b = blockIdx.x;
    __shared__ float row[512];
    int t = threadIdx.x;
    for (int k = t; k < 512; k += 160) row[k] = o1[(size_t)b * 512 + k];
    __syncthreads();
    int c = t >> 3, sub = t & 7;
    float s = 0.0f;
    for (int k = sub; k < 512; k += 8) s += row[k] * w2[k * NCLS + c];
    s += __shfl_down_sync(0xffffffffu, s, 4);
    s += __shfl_down_sync(0xffffffffu, s, 2);
    s += __shfl_down_sync(0xffffffffu, s, 1);
    if (sub == 0) out[b * NCLS + c] = s + b2[c];
}

// ---- launch ----
extern "C" void kernel_launch(void* const* d_in, const int* in_sizes, int n_in,
                              void* d_out, int out_size) {
    const float* wifi      = (const float*)d_in[0];
    const float* rfid      = (const float*)d_in[1];
    const float* gate_w1   = (const float*)d_in[2];
    const float* gate_b1   = (const float*)d_in[3];
    const float* gate_ln_g = (const float*)d_in[4];
    const float* gate_ln_b = (const float*)d_in[5];
    const float* gate_w2   = (const float*)d_in[6];
    const float* gate_b2   = (const float*)d_in[7];
    const float* exp_w1    = (const float*)d_in[8];
    const float* exp_b1    = (const float*)d_in[9];
    const float* exp_bn1_g = (const float*)d_in[10];
    const float* exp_bn1_b = (const float*)d_in[11];
    const float* exp_bn1_m = (const float*)d_in[12];
    const float* exp_bn1_v = (const float*)d_in[13];
    const float* exp_w2    = (const float*)d_in[14];
    const float* exp_b2    = (const float*)d_in[15];
    const float* exp_bn2_g = (const float*)d_in[16];
    const float* exp_bn2_b = (const float*)d_in[17];
    const float* exp_bn2_m = (const float*)d_in[18];
    const float* exp_bn2_v = (const float*)d_in[19];
    const float* fin_w1    = (const float*)d_in[20];
    const float* fin_b1    = (const float*)d_in[21];
    const float* fin_bn_g  = (const float*)d_in[22];
    const float* fin_bn_b  = (const float*)d_in[23];
    const float* fin_bn_m  = (const float*)d_in[24];
    const float* fin_bn_v  = (const float*)d_in[25];
    const float* fin_w2    = (const float*)d_in[26];
    const float* fin_b2    = (const float*)d_in[27];
    float* out = (float*)d_out;

    float *combined, *g1, *tw, *h1, *h2, *fused, *o1;
    int *tidx, *counts, *cursor, *offsets, *rowinfo;
    __nv_bfloat16 *ew1h, *ew1l, *ew2h, *ew2l, *fw1h, *fw1l;
    cudaGetSymbolAddress((void**)&combined, g_combined);
    cudaGetSymbolAddress((void**)&g1,       g_g1);
    cudaGetSymbolAddress((void**)&tidx,     g_tidx);
    cudaGetSymbolAddress((void**)&tw,       g_tw);
    cudaGetSymbolAddress((void**)&counts,   g_counts);
    cudaGetSymbolAddress((void**)&cursor,   g_cursor);
    cudaGetSymbolAddress((void**)&offsets,  g_offsets);
    cudaGetSymbolAddress((void**)&rowinfo,  g_rowinfo);
    cudaGetSymbolAddress((void**)&h1,       g_h1);
    cudaGetSymbolAddress((void**)&h2,       g_h2);
    cudaGetSymbolAddress((void**)&fused,    g_fused);
    cudaGetSymbolAddress((void**)&o1,       g_o1);
    cudaGetSymbolAddress((void**)&ew1h,     g_ew1h);
    cudaGetSymbolAddress((void**)&ew1l,     g_ew1l);
    cudaGetSymbolAddress((void**)&ew2h,     g_ew2h);
    cudaGetSymbolAddress((void**)&ew2l,     g_ew2l);
    cudaGetSymbolAddress((void**)&fw1h,     g_fw1h);
    cudaGetSymbolAddress((void**)&fw1l,     g_fw1l);

    cudaFuncSetAttribute(w_gemm<true, true, false, true>,
                         cudaFuncAttributeMaxDynamicSharedMemorySize, WG_SMEM);
    cudaFuncSetAttribute(w_gemm<true, false, true, true>,
                         cudaFuncAttributeMaxDynamicSharedMemorySize, WG_SMEM);
    cudaFuncSetAttribute(w_gemm<false, false, false, true>,
                         cudaFuncAttributeMaxDynamicSharedMemorySize, WG_SMEM);

    // weight split (pure bandwidth, ~30us)
    wsplit_kernel<<<dim3(32, 16, NEXP), dim3(32, 8)>>>(exp_w1, ew1h, ew1l, DIN, HDIM);
    wsplit_kernel<<<dim3(32, 32, NEXP), dim3(32, 8)>>>(exp_w2, ew2h, ew2l, HDIM, HDIM);
    wsplit_kernel<<<dim3(16, 32, 1),    dim3(32, 8)>>>(fin_w1, fw1h, fw1l, HDIM, 512);

    // 1. concat
    concat_kernel<<<(BTOK * DIN + 255) / 256, 256>>>(wifi, rfid, combined);
    // 2. gate GEMM1 (exact fp32)
    gate_gemm<<<dim3(32, 8), 256>>>(combined, gate_w1, g1, gate_b1);
    // 3. LN + GELU
    ln_gelu_kernel<<<BTOK, 256>>>(g1, gate_ln_g, gate_ln_b);
    // 4. gate top-4
    reset_kernel<<<1, 32>>>(counts);
    gate_topk_kernel<<<BTOK, 128>>>(g1, gate_w2, gate_b2, tidx, tw, counts);
    // 5. dispatch
    scan_kernel<<<1, 1>>>(counts, offsets, cursor);
    scatter_kernel<<<(BTOK * KSEL + 255) / 256, 256>>>(tidx, cursor, rowinfo);
    // 6. expert GEMM1 (HMMA 3-pass, gather, BN1+GELU); per-expert M <= 4096 -> 32 m-tiles
    w_gemm<true, true, false, true><<<dim3(32, 8, NEXP), 256, WG_SMEM>>>(
        combined, ew1h, ew1l, h1, 0, HDIM, DIN,
        offsets, rowinfo, exp_b1, exp_bn1_g, exp_bn1_b, exp_bn1_m, exp_bn1_v);
    // 7. expert GEMM2 (HMMA 3-pass, scatter, BN2+GELU)
    w_gemm<true, false, true, true><<<dim3(32, 8, NEXP), 256, WG_SMEM>>>(
        h1, ew2h, ew2l, h2, 0, HDIM, HDIM,
        offsets, rowinfo, exp_b2, exp_bn2_g, exp_bn2_b, exp_bn2_m, exp_bn2_v);
    // 8. combine
    combine_kernel<<<(BTOK * HDIM + 255) / 256, 256>>>(h2, tw, fused);
    // 9. final GEMM1 (HMMA 3-pass, BN+GELU)
    w_gemm<false, false, false, true><<<dim3(32, 4, 1), 256, WG_SMEM>>>(
        fused, fw1h, fw1l, o1, BTOK, 512, HDIM,
        nullptr, nullptr, fin_b1, fin_bn_g, fin_bn_b, fin_bn_m, fin_bn_v);
    // 10. head
    final_kernel<<<BTOK, 160>>>(o1, fin_w2, fin_b2, out);
}

// round 9
// speedup vs baseline: 1.7123x; 1.0067x over previous
#include <cuda_runtime.h>
#include <cuda_bf16.h>
#include <math.h>
#include <stdint.h>

#define BTOK 4096
#define DIN  512
#define HDIM 1024
#define NEXP 16
#define KSEL 4
#define NCLS 20
#define EPSN 1e-5f

// ---- device scratch (no allocation allowed) ----
__device__ float g_combined[BTOK * DIN];            // fp32 (gate)
__device__ __nv_bfloat16 g_combh[BTOK * DIN];       // pre-split A for GEMM1
__device__ __nv_bfloat16 g_combl[BTOK * DIN];
__device__ float g_g1[BTOK * HDIM];
__device__ int   g_tidx[BTOK * KSEL];
__device__ float g_tw[BTOK * KSEL];
__device__ int   g_counts[NEXP];
__device__ int   g_cursor[NEXP];
__device__ int   g_offsets[NEXP + 1];
__device__ int   g_rowinfo[BTOK * KSEL];
__device__ __nv_bfloat16 g_h1h[BTOK * KSEL * HDIM]; // GEMM1 out, pre-split for GEMM2
__device__ __nv_bfloat16 g_h1l[BTOK * KSEL * HDIM];
__device__ float g_h2[BTOK * KSEL * HDIM];
__device__ __nv_bfloat16 g_fusedh[BTOK * HDIM];     // combine out, pre-split for final
__device__ __nv_bfloat16 g_fusedl[BTOK * HDIM];
__device__ float g_o1[BTOK * 512];
__device__ __nv_bfloat16 g_ew1h[NEXP * DIN * HDIM];
__device__ __nv_bfloat16 g_ew1l[NEXP * DIN * HDIM];
__device__ __nv_bfloat16 g_ew2h[NEXP * HDIM * HDIM];
__device__ __nv_bfloat16 g_ew2l[NEXP * HDIM * HDIM];
__device__ __nv_bfloat16 g_fw1h[HDIM * 512];
__device__ __nv_bfloat16 g_fw1l[HDIM * 512];

__device__ __forceinline__ float gelu_f(float x) {
    return 0.5f * x * (1.0f + erff(x * 0.70710678118654752440f));
}
__device__ __forceinline__ uint32_t smem_u32(const void* p) {
    uint32_t a;
    asm("{ .reg .u64 t; cvta.to.shared.u64 t, %1; cvt.u32.u64 %0, t; }" : "=r"(a) : "l"(p));
    return a;
}
__device__ __forceinline__ uint4 ldm4(uint32_t addr) {
    uint4 r;
    asm volatile("ldmatrix.sync.aligned.m8n8.x4.shared.b16 {%0,%1,%2,%3}, [%4];"
                 : "=r"(r.x), "=r"(r.y), "=r"(r.z), "=r"(r.w) : "r"(addr));
    return r;
}
__device__ __forceinline__ void mma_bf16(float* c, const uint4& a, uint32_t b0, uint32_t b1) {
    asm volatile(
        "mma.sync.aligned.m16n8k16.row.col.f32.bf16.bf16.f32 "
        "{%0,%1,%2,%3}, {%4,%5,%6,%7}, {%8,%9}, {%0,%1,%2,%3};"
        : "+f"(c[0]), "+f"(c[1]), "+f"(c[2]), "+f"(c[3])
        : "r"(a.x), "r"(a.y), "r"(a.z), "r"(a.w), "r"(b0), "r"(b1));
}
__device__ __forceinline__ uint32_t pk(__nv_bfloat16 a, __nv_bfloat16 b) {
    return (uint32_t)__bfloat16_as_ushort(a) | ((uint32_t)__bfloat16_as_ushort(b) << 16);
}
__device__ __forceinline__ void split2(float x, __nv_bfloat16& h, __nv_bfloat16& l) {
    h = __float2bfloat16_rn(x);
    l = __float2bfloat16_rn(x - __bfloat162float(h));
}

// ---- concat: fp32 + pre-split bf16 planes ----
__global__ void concat_kernel(const float* __restrict__ wifi, const float* __restrict__ rfid,
                              float* __restrict__ comb,
                              __nv_bfloat16* __restrict__ ch, __nv_bfloat16* __restrict__ cl) {
    int i = blockIdx.x * 256 + threadIdx.x;
    if (i < BTOK * DIN) {
        int b = i >> 9, c = i & 511;
        float v = (c < 256) ? wifi[b * 256 + c] : rfid[b * 256 + (c - 256)];
        comb[i] = v;
        __nv_bfloat16 h, l; split2(v, h, l);
        ch[i] = h; cl[i] = l;
    }
}

// ---- weight transpose + bf16 hi/lo split: W[e,K,N] -> T{h,l}[e,N,K] ----
__global__ void wsplit_kernel(const float* __restrict__ W,
                              __nv_bfloat16* __restrict__ Th, __nv_bfloat16* __restrict__ Tl,
                              int K, int N) {
    __shared__ float tile[32][33];
    size_t base = (size_t)blockIdx.z * K * N;
    int k0 = blockIdx.y * 32, n0 = blockIdx.x * 32;
    int tx = threadIdx.x, ty = threadIdx.y;
#pragma unroll
    for (int i = 0; i < 32; i += 8)
        tile[ty + i][tx] = W[base + (size_t)(k0 + ty + i) * N + n0 + tx];
    __syncthreads();
#pragma unroll
    for (int i = 0; i < 32; i += 8) {
        int n = n0 + ty + i, k = k0 + tx;
        __nv_bfloat16 h, l; split2(tile[tx][ty + i], h, l);
        Th[base + (size_t)n * K + k] = h;
        Tl[base + (size_t)n * K + k] = l;
    }
}

// ---------------------------------------------------------------------------
// bf16 3-pass HMMA GEMM with PRE-SPLIT A: C = A @ B
// A: two bf16 planes [M,K] row-major. B: two bf16 planes [N,K].
// CTA 128x128, 256 thr (8 warps 4Mx2N), k-chunk 32, double-buffered SMEM,
// 80B padded rows. OUTS: write C as bf16 hi/lo planes instead of fp32.
// SMEM buffer: Ah@0 Al@10240 Bh@20480 Bl@30720 (40960/buffer).
// ---------------------------------------------------------------------------
static constexpr int WG_SMEM = 2 * 40960;

template<bool SEG, bool GATHER, bool SCATTER, bool BN, bool OUTS>
__global__ void __launch_bounds__(256, 1) w_gemm(
    const __nv_bfloat16* __restrict__ Ahp, const __nv_bfloat16* __restrict__ Alp,
    const __nv_bfloat16* __restrict__ Bhp, const __nv_bfloat16* __restrict__ Blp,
    float* __restrict__ C, __nv_bfloat16* __restrict__ Ch, __nv_bfloat16* __restrict__ Cl,
    int Mfixed, int N, int K,
    const int* __restrict__ offsets, const int* __restrict__ rowinfo,
    const float* __restrict__ bias,
    const float* __restrict__ bng, const float* __restrict__ bnb,
    const float* __restrict__ bnm, const float* __restrict__ bnv)
{
    extern __shared__ __align__(16) char sm[];
    int m0 = 0, M = Mfixed;
    if (SEG) {
        int e = blockIdx.z;
        m0 = offsets[e];
        M  = offsets[e + 1] - m0;
        size_t wo = (size_t)e * K * N;
        Bhp += wo; Blp += wo;
        bias += (size_t)e * N;
        if (BN) { bng += (size_t)e * N; bnb += (size_t)e * N;
                  bnm += (size_t)e * N; bnv += (size_t)e * N; }
    }
    const int mtile = blockIdx.x * 128;
    if (mtile >= M) return;
    const int ntile = blockIdx.y * 128;

    const int tid = threadIdx.x, lane = tid & 31, wid = tid >> 5;
    const int warpM = wid & 3, warpN = wid >> 2;
    const uint32_t smBase = smem_u32(sm);

    // A fill: 4 rows/thread, 8B (4 bf16) per plane per row
    const int acg = tid & 7;
    const __nv_bfloat16* aPh[4]; const __nv_bfloat16* aPl[4];
    bool aval[4]; uint32_t aDst[4];
#pragma unroll
    for (int i = 0; i < 4; i++) {
        int row = (tid >> 3) + i * 32;
        bool v = (mtile + row) < M;
        aval[i] = v;
        int tok = 0;
        if (v) { int gr = m0 + mtile + row; tok = GATHER ? (rowinfo[gr] >> 2) : gr; }
        size_t off = (size_t)tok * K + acg * 4;
        aPh[i] = Ahp + off; aPl[i] = Alp + off;
        aDst[i] = (uint32_t)(row * 80 + acg * 8);
    }
    // B fill: 2 planes x 128 rows x 4 groups of 16B
    const __nv_bfloat16* bPtr[4]; uint32_t bDst[4];
#pragma unroll
    for (int i = 0; i < 4; i++) {
        int idx = tid + (i << 8);
        int plane = idx >> 9, f = idx & 511;
        int row = f >> 2, cg = f & 3;
        bPtr[i] = (plane ? Blp : Bhp) + (size_t)(ntile + row) * K + cg * 8;
        bDst[i] = (plane ? 30720u : 20480u) + (uint32_t)(row * 80 + cg * 16);
    }

    const int qa = lane >> 3, ra = lane & 7;
    const int lrow = ((qa & 1) << 3) + ra;
    const int lcolB = ((qa >> 1) << 3) * 2;
    const uint32_t aFragOff = (uint32_t)((warpM * 32 + lrow) * 80) + lcolB;
    const uint32_t bFragOff = (uint32_t)((warpN * 64 + lrow) * 80) + lcolB + 20480u;

    float acc[2][8][4];
#pragma unroll
    for (int mt = 0; mt < 2; mt++)
#pragma unroll
        for (int nt = 0; nt < 8; nt++)
#pragma unroll
            for (int q = 0; q < 4; q++) acc[mt][nt][q] = 0.0f;

    const int NC = K >> 5;
    const uint2 z2 = make_uint2(0u, 0u);

    // preload chunk 0
    {
        char* base = sm;
#pragma unroll
        for (int i = 0; i < 4; i++) {
            *(uint2*)(base + aDst[i])         = aval[i] ? *(const uint2*)aPh[i] : z2;
            *(uint2*)(base + 10240 + aDst[i]) = aval[i] ? *(const uint2*)aPl[i] : z2;
        }
#pragma unroll
        for (int i = 0; i < 4; i++)
            *(uint4*)(base + bDst[i]) = *(const uint4*)bPtr[i];
    }
    __syncthreads();

    for (int c = 0; c < NC; c++) {
        uint2 aRh[4], aRl[4]; uint4 bR[4];
        const bool pf = (c + 1) < NC;
        if (pf) {
            const int kc = (c + 1) << 5;
#pragma unroll
            for (int i = 0; i < 4; i++) {
                aRh[i] = aval[i] ? *(const uint2*)(aPh[i] + kc) : z2;
                aRl[i] = aval[i] ? *(const uint2*)(aPl[i] + kc) : z2;
            }
#pragma unroll
            for (int i = 0; i < 4; i++)
                bR[i] = *(const uint4*)(bPtr[i] + kc);
        }
        const uint32_t bb = smBase + (uint32_t)(c & 1) * 40960u;
#pragma unroll
        for (int ks = 0; ks < 2; ks++) {
            const uint32_t kso = ks * 32;
            uint4 ah[2], al[2];
#pragma unroll
            for (int mt = 0; mt < 2; mt++) {
                uint32_t ao = bb + aFragOff + mt * 1280u + kso;
                ah[mt] = ldm4(ao);
                al[mt] = ldm4(ao + 10240u);
            }
            uint32_t bh[8][2], bl[8][2];
#pragma unroll
            for (int np = 0; np < 4; np++) {
                uint32_t bo = bb + bFragOff + np * 1280u + kso;
                uint4 h = ldm4(bo);
                uint4 l = ldm4(bo + 10240u);
                bh[2*np][0] = h.x; bh[2*np][1] = h.z;
                bh[2*np+1][0] = h.y; bh[2*np+1][1] = h.w;
                bl[2*np][0] = l.x; bl[2*np][1] = l.z;
                bl[2*np+1][0] = l.y; bl[2*np+1][1] = l.w;
            }
#pragma unroll
            for (int mt = 0; mt < 2; mt++)
#pragma unroll
                for (int nt = 0; nt < 8; nt++) {
                    mma_bf16(acc[mt][nt], ah[mt], bh[nt][0], bh[nt][1]);
                    mma_bf16(acc[mt][nt], ah[mt], bl[nt][0], bl[nt][1]);
                    mma_bf16(acc[mt][nt], al[mt], bh[nt][0], bh[nt][1]);
                }
        }
        if (pf) {
            char* base = sm + ((c + 1) & 1) * 40960;
#pragma unroll
            for (int i = 0; i < 4; i++) {
                *(uint2*)(base + aDst[i])         = aRh[i];
                *(uint2*)(base + 10240 + aDst[i]) = aRl[i];
            }
#pragma unroll
            for (int i = 0; i < 4; i++)
                *(uint4*)(base + bDst[i]) = bR[i];
        }
        __syncthreads();
    }

    // epilogue: bias (+BN+GELU); output fp32 or split bf16 planes
    const int g = lane >> 2, tt = lane & 3;
#pragma unroll
    for (int mt = 0; mt < 2; mt++) {
#pragma unroll
        for (int half = 0; half < 2; half++) {
            int rl = mtile + warpM * 32 + mt * 16 + half * 8 + g;
            if (rl < M) {
                int gr = m0 + rl;
                int crow = SCATTER ? rowinfo[gr] : gr;
                size_t rowoff = (size_t)crow * N;
#pragma unroll
                for (int nt = 0; nt < 8; nt++) {
                    int cn = ntile + warpN * 64 + nt * 8 + tt * 2;
                    float x0 = acc[mt][nt][half * 2 + 0] + __ldg(bias + cn);
                    float x1 = acc[mt][nt][half * 2 + 1] + __ldg(bias + cn + 1);
                    if (BN) {
                        x0 = gelu_f((x0 - __ldg(bnm + cn)) * rsqrtf(__ldg(bnv + cn) + EPSN)
                                    * __ldg(bng + cn) + __ldg(bnb + cn));
                        x1 = gelu_f((x1 - __ldg(bnm + cn + 1)) * rsqrtf(__ldg(bnv + cn + 1) + EPSN)
                                    * __ldg(bng + cn + 1) + __ldg(bnb + cn + 1));
                    }
                    if (OUTS) {
                        __nv_bfloat16 h0, l0, h1v, l1v;
                        split2(x0, h0, l0); split2(x1, h1v, l1v);
                        *(uint32_t*)(Ch + rowoff + cn) = pk(h0, h1v);
                        *(uint32_t*)(Cl + rowoff + cn) = pk(l0, l1v);
                    } else {
                        *(float2*)(C + rowoff + cn) = make_float2(x0, x1);
                    }
                }
            }
        }
    }
}

// ---- fp32 gate GEMM (selection-exact): [4096,512]@[512,1024]+b ----
__global__ void __launch_bounds__(256, 2) gate_gemm(
    const float* __restrict__ A, const float* __restrict__ Bw,
    float* __restrict__ C, const float* __restrict__ bias)
{
    const int N = HDIM, K = DIN;
    const int mtile = blockIdx.x * 128, ntile = blockIdx.y * 128;
    __shared__ float As[16][128], Bs[16][128];
    const int tid = threadIdx.x, tx = tid & 15, ty = tid >> 4;
    const int arow0 = tid >> 2, arow1 = arow0 + 64, ak4 = (tid & 3) << 2;
    const size_t ab0 = (size_t)(mtile + arow0) * K, ab1 = (size_t)(mtile + arow1) * K;
    const int brow = tid >> 5, bc4 = (tid & 31) << 2;
    float acc[8][8];
#pragma unroll
    for (int i = 0; i < 8; i++)
#pragma unroll
        for (int j = 0; j < 8; j++) acc[i][j] = 0.0f;
    for (int kt = 0; kt < K; kt += 16) {
        float4 a0 = *(const float4*)(A + ab0 + kt + ak4);
        float4 a1 = *(const float4*)(A + ab1 + kt + ak4);
        As[ak4 + 0][arow0] = a0.x; As[ak4 + 1][arow0] = a0.y;
        As[ak4 + 2][arow0] = a0.z; As[ak4 + 3][arow0] = a0.w;
        As[ak4 + 0][arow1] = a1.x; As[ak4 + 1][arow1] = a1.y;
        As[ak4 + 2][arow1] = a1.z; As[ak4 + 3][arow1] = a1.w;
        *(float4*)&Bs[brow    ][bc4] = *(const float4*)(Bw + (size_t)(kt + brow    ) * N + ntile + bc4);
        *(float4*)&Bs[brow + 8][bc4] = *(const float4*)(Bw + (size_t)(kt + brow + 8) * N + ntile + bc4);
        __syncthreads();
#pragma unroll
        for (int k = 0; k < 16; k++) {
            float af[8], bf[8];
            *(float4*)&af[0] = *(float4*)&As[k][ty * 8];
            *(float4*)&af[4] = *(float4*)&As[k][ty * 8 + 4];
            *(float4*)&bf[0] = *(float4*)&Bs[k][tx * 8];
            *(float4*)&bf[4] = *(float4*)&Bs[k][tx * 8 + 4];
#pragma unroll
            for (int i = 0; i < 8; i++)
#pragma unroll
                for (int j = 0; j < 8; j++) acc[i][j] += af[i] * bf[j];
        }
        __syncthreads();
    }
    const int cn = ntile + tx * 8;
    float bi[8];
    *(float4*)&bi[0] = *(const float4*)(bias + cn);
    *(float4*)&bi[4] = *(const float4*)(bias + cn + 4);
#pragma unroll
    for (int i = 0; i < 8; i++) {
        float v[8];
#pragma unroll
        for (int j = 0; j < 8; j++) v[j] = acc[i][j] + bi[j];
        float* cp = C + (size_t)(mtile + ty * 8 + i) * N + cn;
        *(float4*)cp = *(float4*)&v[0];
        *(float4*)(cp + 4) = *(float4*)&v[4];
    }
}

// ---- LayerNorm + GELU (in place, row=1024) ----
__global__ void ln_gelu_kernel(float* __restrict__ x, const float* __restrict__ g,
                               const float* __restrict__ b) {
    int row = blockIdx.x;
    float* xr = x + (size_t)row * HDIM;
    int t = threadIdx.x;
    float4 v = *(float4*)&xr[t * 4];
    float s = v.x + v.y + v.z + v.w;
    float q = v.x * v.x + v.y * v.y + v.z * v.z + v.w * v.w;
#pragma unroll
    for (int o = 16; o; o >>= 1) {
        s += __shfl_down_sync(0xffffffffu, s, o);
        q += __shfl_down_sync(0xffffffffu, q, o);
    }
    __shared__ float ss[8], qq[8];
    int w = t >> 5, l = t & 31;
    if (l == 0) { ss[w] = s; qq[w] = q; }
    __syncthreads();
    if (w == 0) {
        s = (l < 8) ? ss[l] : 0.0f;
        q = (l < 8) ? qq[l] : 0.0f;
#pragma unroll
        for (int o = 4; o; o >>= 1) {
            s += __shfl_down_sync(0xffffffffu, s, o);
            q += __shfl_down_sync(0xffffffffu, q, o);
        }
        if (l == 0) { ss[0] = s; qq[0] = q; }
    }
    __syncthreads();
    float mu  = ss[0] * (1.0f / HDIM);
    float var = qq[0] * (1.0f / HDIM) - mu * mu;
    float r = rsqrtf(var + EPSN);
    float4 gv = *(const float4*)&g[t * 4];
    float4 bv = *(const float4*)&b[t * 4];
    v.x = gelu_f((v.x - mu) * r * gv.x + bv.x);
    v.y = gelu_f((v.y - mu) * r * gv.y + bv.y);
    v.z = gelu_f((v.z - mu) * r * gv.z + bv.z);
    v.w = gelu_f((v.w - mu) * r * gv.w + bv.w);
    *(float4*)&xr[t * 4] = v;
}

// ---- gate logits + softmax + top4 + renorm ----
__global__ void gate_topk_kernel(const float* __restrict__ g1, const float* __restrict__ w2,
                                 const float* __restrict__ b2, int* __restrict__ tidx,
                                 float* __restrict__ tw, int* __restrict__ counts) {
    int b = blockIdx.x, t = threadIdx.x;
    int e = t >> 3, sub = t & 7;
    const float* row = g1 + (size_t)b * HDIM;
    float s = 0.0f;
    for (int k = sub; k < HDIM; k += 8) s += row[k] * w2[k * NEXP + e];
    s += __shfl_down_sync(0xffffffffu, s, 4);
    s += __shfl_down_sync(0xffffffffu, s, 2);
    s += __shfl_down_sync(0xffffffffu, s, 1);
    __shared__ float logit[NEXP];
    if (sub == 0) logit[e] = s + b2[e];
    __syncthreads();
    if (t == 0) {
        float mx = -1e30f;
        for (int i = 0; i < NEXP; i++) mx = fmaxf(mx, logit[i]);
        float p[NEXP], sum = 0.0f;
        for (int i = 0; i < NEXP; i++) { p[i] = expf(logit[i] - mx); sum += p[i]; }
        float inv = 1.0f / sum;
        bool used[NEXP];
        for (int i = 0; i < NEXP; i++) used[i] = false;
        int idx[KSEL]; float val[KSEL];
        for (int tk = 0; tk < KSEL; tk++) {
            int best = -1; float bv = -1e30f;
            for (int i = 0; i < NEXP; i++)
                if (!used[i] && p[i] > bv) { bv = p[i]; best = i; }
            used[best] = true; idx[tk] = best; val[tk] = bv * inv;
        }
        float m2 = val[0], e2[KSEL], s2 = 0.0f;
        for (int tk = 0; tk < KSEL; tk++) { e2[tk] = expf(val[tk] - m2); s2 += e2[tk]; }
        float inv2 = 1.0f / s2;
        for (int tk = 0; tk < KSEL; tk++) {
            tidx[b * KSEL + tk] = idx[tk];
            tw[b * KSEL + tk]   = e2[tk] * inv2;
            atomicAdd(&counts[idx[tk]], 1);
        }
    }
}

// ---- dispatch bookkeeping ----
__global__ void reset_kernel(int* __restrict__ counts) {
    if (threadIdx.x < NEXP) counts[threadIdx.x] = 0;
}
__global__ void scan_kernel(const int* __restrict__ counts, int* __restrict__ offsets,
                            int* __restrict__ cursor) {
    if (threadIdx.x == 0) {
        int acc = 0;
        for (int e = 0; e < NEXP; e++) { offsets[e] = acc; cursor[e] = acc; acc += counts[e]; }
        offsets[NEXP] = acc;
    }
}
__global__ void scatter_kernel(const int* __restrict__ tidx, int* __restrict__ cursor,
                               int* __restrict__ rowinfo) {
    int i = blockIdx.x * 256 + threadIdx.x;
    if (i < BTOK * KSEL) {
        int pos = atomicAdd(&cursor[tidx[i]], 1);
        rowinfo[pos] = i;
    }
}

// ---- weighted top-k combine -> pre-split fused planes ----
__global__ void combine_kernel(const float* __restrict__ h2, const float* __restrict__ tw,
                               __nv_bfloat16* __restrict__ fh, __nv_bfloat16* __restrict__ fl) {
    int idx = blockIdx.x * 256 + threadIdx.x;
    if (idx < BTOK * HDIM) {
        int b = idx >> 10, h = idx & (HDIM - 1);
        const float* base = h2 + ((size_t)b * KSEL) * HDIM + h;
        const float* w = tw + b * KSEL;
        float v = w[0] * base[0] + w[1] * base[HDIM]
                + w[2] * base[2 * HDIM] + w[3] * base[3 * HDIM];
        __nv_bfloat16 hh, ll; split2(v, hh, ll);
        fh[idx] = hh; fl[idx] = ll;
    }
}

// ---- final head GEMM [4096,512]x[512,20] ----
__global__ void final_kernel(const float* __restrict__ o1, const float* __restrict__ w2,
                             const float* __restrict__ b2, float* __restrict__ out) {
    int b = blockIdx.x;
    __shared__ float row[512];
    int t = threadIdx.x;
    for (int k = t; k < 512; k += 160) row[k] = o1[(size_t)b * 512 + k];
    __syncthreads();
    int c = t >> 3, sub = t & 7;
    float s = 0.0f;
    for (int k = sub; k < 512; k += 8) s += row[k] * w2[k * NCLS + c];
    s += __shfl_down_sync(0xffffffffu, s, 4);
    s += __shfl_down_sync(0xffffffffu, s, 2);
    s += __shfl_down_sync(0xffffffffu, s, 1);
    if (sub == 0) out[b * NCLS + c] = s + b2[c];
}

// ---- launch ----
extern "C" void kernel_launch(void* const* d_in, const int* in_sizes, int n_in,
                              void* d_out, int out_size) {
    const float* wifi      = (const float*)d_in[0];
    const float* rfid      = (const float*)d_in[1];
    const float* gate_w1   = (const float*)d_in[2];
    const float* gate_b1   = (const float*)d_in[3];
    const float* gate_ln_g = (const float*)d_in[4];
    const float* gate_ln_b = (const float*)d_in[5];
    const float* gate_w2   = (const float*)d_in[6];
    const float* gate_b2   = (const float*)d_in[7];
    const float* exp_w1    = (const float*)d_in[8];
    const float* exp_b1    = (const float*)d_in[9];
    const float* exp_bn1_g = (const float*)d_in[10];
    const float* exp_bn1_b = (const float*)d_in[11];
    const float* exp_bn1_m = (const float*)d_in[12];
    const float* exp_bn1_v = (const float*)d_in[13];
    const float* exp_w2    = (const float*)d_in[14];
    const float* exp_b2    = (const float*)d_in[15];
    const float* exp_bn2_g = (const float*)d_in[16];
    const float* exp_bn2_b = (const float*)d_in[17];
    const float* exp_bn2_m = (const float*)d_in[18];
    const float* exp_bn2_v = (const float*)d_in[19];
    const float* fin_w1    = (const float*)d_in[20];
    const float* fin_b1    = (const float*)d_in[21];
    const float* fin_bn_g  = (const float*)d_in[22];
    const float* fin_bn_b  = (const float*)d_in[23];
    const float* fin_bn_m  = (const float*)d_in[24];
    const float* fin_bn_v  = (const float*)d_in[25];
    const float* fin_w2    = (const float*)d_in[26];
    const float* fin_b2    = (const float*)d_in[27];
    float* out = (float*)d_out;

    float *combined, *g1, *tw, *h2, *o1;
    int *tidx, *counts, *cursor, *offsets, *rowinfo;
    __nv_bfloat16 *combh, *combl, *h1h, *h1l, *fusedh, *fusedl;
    __nv_bfloat16 *ew1h, *ew1l, *ew2h, *ew2l, *fw1h, *fw1l;
    cudaGetSymbolAddress((void**)&combined, g_combined);
    cudaGetSymbolAddress((void**)&combh,    g_combh);
    cudaGetSymbolAddress((void**)&combl,    g_combl);
    cudaGetSymbolAddress((void**)&g1,       g_g1);
    cudaGetSymbolAddress((void**)&tidx,     g_tidx);
    cudaGetSymbolAddress((void**)&tw,       g_tw);
    cudaGetSymbolAddress((void**)&counts,   g_counts);
    cudaGetSymbolAddress((void**)&cursor,   g_cursor);
    cudaGetSymbolAddress((void**)&offsets,  g_offsets);
    cudaGetSymbolAddress((void**)&rowinfo,  g_rowinfo);
    cudaGetSymbolAddress((void**)&h1h,      g_h1h);
    cudaGetSymbolAddress((void**)&h1l,      g_h1l);
    cudaGetSymbolAddress((void**)&h2,       g_h2);
    cudaGetSymbolAddress((void**)&fusedh,   g_fusedh);
    cudaGetSymbolAddress((void**)&fusedl,   g_fusedl);
    cudaGetSymbolAddress((void**)&o1,       g_o1);
    cudaGetSymbolAddress((void**)&ew1h,     g_ew1h);
    cudaGetSymbolAddress((void**)&ew1l,     g_ew1l);
    cudaGetSymbolAddress((void**)&ew2h,     g_ew2h);
    cudaGetSymbolAddress((void**)&ew2l,     g_ew2l);
    cudaGetSymbolAddress((void**)&fw1h,     g_fw1h);
    cudaGetSymbolAddress((void**)&fw1l,     g_fw1l);

    cudaFuncSetAttribute(w_gemm<true, true, false, true, true>,
                         cudaFuncAttributeMaxDynamicSharedMemorySize, WG_SMEM);
    cudaFuncSetAttribute(w_gemm<true, false, true, true, false>,
                         cudaFuncAttributeMaxDynamicSharedMemorySize, WG_SMEM);
    cudaFuncSetAttribute(w_gemm<false, false, false, true, false>,
                         cudaFuncAttributeMaxDynamicSharedMemorySize, WG_SMEM);

    // weight split (pure bandwidth)
    wsplit_kernel<<<dim3(32, 16, NEXP), dim3(32, 8)>>>(exp_w1, ew1h, ew1l, DIN, HDIM);
    wsplit_kernel<<<dim3(32, 32, NEXP), dim3(32, 8)>>>(exp_w2, ew2h, ew2l, HDIM, HDIM);
    wsplit_kernel<<<dim3(16, 32, 1),    dim3(32, 8)>>>(fin_w1, fw1h, fw1l, HDIM, 512);

    // 1. concat (fp32 + pre-split planes)
    concat_kernel<<<(BTOK * DIN + 255) / 256, 256>>>(wifi, rfid, combined, combh, combl);
    // 2. gate GEMM1 (exact fp32)
    gate_gemm<<<dim3(32, 8), 256>>>(combined, gate_w1, g1, gate_b1);
    // 3. LN + GELU
    ln_gelu_kernel<<<BTOK, 256>>>(g1, gate_ln_g, gate_ln_b);
    // 4. gate top-4
    reset_kernel<<<1, 32>>>(counts);
    gate_topk_kernel<<<BTOK, 128>>>(g1, gate_w2, gate_b2, tidx, tw, counts);
    // 5. dispatch
    scan_kernel<<<1, 1>>>(counts, offsets, cursor);
    scatter_kernel<<<(BTOK * KSEL + 255) / 256, 256>>>(tidx, cursor, rowinfo);
    // 6. expert GEMM1 (gather, BN1+GELU, split output)
    w_gemm<true, true, false, true, true><<<dim3(32, 8, NEXP), 256, WG_SMEM>>>(
        combh, combl, ew1h, ew1l, nullptr, h1h, h1l, 0, HDIM, DIN,
        offsets, rowinfo, exp_b1, exp_bn1_g, exp_bn1_b, exp_bn1_m, exp_bn1_v);
    // 7. expert GEMM2 (scatter, BN2+GELU, fp32 output)
    w_gemm<true, false, true, true, false><<<dim3(32, 8, NEXP), 256, WG_SMEM>>>(
        h1h, h1l, ew2h, ew2l, h2, nullptr, nullptr, 0, HDIM, HDIM,
        offsets, rowinfo, exp_b2, exp_bn2_g, exp_bn2_b, exp_bn2_m, exp_bn2_v);
    // 8. combine -> pre-split fused planes
    combine_kernel<<<(BTOK * HDIM + 255) / 256, 256>>>(h2, tw, fusedh, fusedl);
    // 9. final GEMM1 (BN+GELU, fp32 output)
    w_gemm<false, false, false, true, false><<<dim3(32, 4, 1), 256, WG_SMEM>>>(
        fusedh, fusedl, fw1h, fw1l, o1, nullptr, nullptr, BTOK, 512, HDIM,
        nullptr, nullptr, fin_b1, fin_bn_g, fin_bn_b, fin_bn_m, fin_bn_v);
    // 10. head
    final_kernel<<<BTOK, 160>>>(o1, fin_w2, fin_b2, out);
}

// round 10
// speedup vs baseline: 2.1126x; 1.2338x over previous
#include <cuda_runtime.h>
#include <cuda_fp16.h>
#include <math.h>
#include <stdint.h>

#define BTOK 4096
#define DIN  512
#define HDIM 1024
#define NEXP 16
#define KSEL 4
#define NCLS 20
#define EPSN 1e-5f

// ---- device scratch (no allocation allowed) ----
__device__ float g_combined[BTOK * DIN];        // fp32 (gate path)
__device__ __half g_combh[BTOK * DIN];          // pre-split A planes (GEMM1)
__device__ __half g_combl[BTOK * DIN];
__device__ float g_g1[BTOK * HDIM];
__device__ int   g_tidx[BTOK * KSEL];
__device__ float g_tw[BTOK * KSEL];
__device__ int   g_counts[NEXP];
__device__ int   g_cursor[NEXP];
__device__ int   g_offsets[NEXP + 1];
__device__ int   g_rowinfo[BTOK * KSEL];
__device__ __half g_h1h[BTOK * KSEL * HDIM];    // GEMM1 out planes (GEMM2 A)
__device__ __half g_h1l[BTOK * KSEL * HDIM];
__device__ float g_h2[BTOK * KSEL * HDIM];
__device__ __half g_fusedh[BTOK * HDIM];        // combine out planes (final A)
__device__ __half g_fusedl[BTOK * HDIM];
__device__ float g_o1[BTOK * 512];
__device__ __half g_ew1f[NEXP * DIN * HDIM];    // single-plane fp16 weights [N,K]
__device__ __half g_ew2f[NEXP * HDIM * HDIM];
__device__ __half g_fw1f[HDIM * 512];

__device__ __forceinline__ float gelu_f(float x) {
    return 0.5f * x * (1.0f + erff(x * 0.70710678118654752440f));
}
__device__ __forceinline__ uint32_t smem_u32(const void* p) {
    uint32_t a;
    asm("{ .reg .u64 t; cvta.to.shared.u64 t, %1; cvt.u32.u64 %0, t; }" : "=r"(a) : "l"(p));
    return a;
}
__device__ __forceinline__ uint4 ldm4(uint32_t addr) {
    uint4 r;
    asm volatile("ldmatrix.sync.aligned.m8n8.x4.shared.b16 {%0,%1,%2,%3}, [%4];"
                 : "=r"(r.x), "=r"(r.y), "=r"(r.z), "=r"(r.w) : "r"(addr));
    return r;
}
__device__ __forceinline__ void mma_fp16(float* c, const uint4& a, uint32_t b0, uint32_t b1) {
    asm volatile(
        "mma.sync.aligned.m16n8k16.row.col.f32.f16.f16.f32 "
        "{%0,%1,%2,%3}, {%4,%5,%6,%7}, {%8,%9}, {%0,%1,%2,%3};"
        : "+f"(c[0]), "+f"(c[1]), "+f"(c[2]), "+f"(c[3])
        : "r"(a.x), "r"(a.y), "r"(a.z), "r"(a.w), "r"(b0), "r"(b1));
}
__device__ __forceinline__ uint32_t pkh(__half a, __half b) {
    return (uint32_t)__half_as_ushort(a) | ((uint32_t)__half_as_ushort(b) << 16);
}
__device__ __forceinline__ void split2h(float x, __half& h, __half& l) {
    h = __float2half_rn(x);
    l = __float2half_rn(x - __half2float(h));
}

// ---- concat: fp32 (gate) + pre-split fp16 planes ----
__global__ void concat_kernel(const float* __restrict__ wifi, const float* __restrict__ rfid,
                              float* __restrict__ comb,
                              __half* __restrict__ ch, __half* __restrict__ cl) {
    int i = blockIdx.x * 256 + threadIdx.x;
    if (i < BTOK * DIN) {
        int b = i >> 9, c = i & 511;
        float v = (c < 256) ? wifi[b * 256 + c] : rfid[b * 256 + (c - 256)];
        comb[i] = v;
        __half h, l; split2h(v, h, l);
        ch[i] = h; cl[i] = l;
    }
}

// ---- weight transpose + fp16 convert: W[e,K,N] -> T[e,N,K] ----
__global__ void wsplit_kernel(const float* __restrict__ W, __half* __restrict__ Tf,
                              int K, int N) {
    __shared__ float tile[32][33];
    size_t base = (size_t)blockIdx.z * K * N;
    int k0 = blockIdx.y * 32, n0 = blockIdx.x * 32;
    int tx = threadIdx.x, ty = threadIdx.y;
#pragma unroll
    for (int i = 0; i < 32; i += 8)
        tile[ty + i][tx] = W[base + (size_t)(k0 + ty + i) * N + n0 + tx];
    __syncthreads();
#pragma unroll
    for (int i = 0; i < 32; i += 8) {
        int n = n0 + ty + i, k = k0 + tx;
        Tf[base + (size_t)n * K + k] = __float2half_rn(tile[tx][ty + i]);
    }
}

// ---------------------------------------------------------------------------
// fp16 2-pass HMMA GEMM: C = A @ B
// A: two fp16 planes [M,K] (exact hi/lo split of fp32); B: one fp16 plane [N,K].
// C = Ah@B + Al@B, fp32 accum. Error ~2^-12 RMS (B rounding), A error 2^-22.
// CTA 128x128, 256 thr (8 warps 4Mx2N), k-chunk 32, double-buffered SMEM,
// 80B padded rows (conflict-free ldmatrix).
// SMEM buffer layout: Ah@0, Al@10240, B@20480 (30720 per buffer).
// ---------------------------------------------------------------------------
static constexpr int WG_SMEM = 2 * 30720;

template<bool SEG, bool GATHER, bool SCATTER, bool BN, bool OUTS>
__global__ void __launch_bounds__(256, 1) w_gemm(
    const __half* __restrict__ Ahp, const __half* __restrict__ Alp,
    const __half* __restrict__ Bp,
    float* __restrict__ C, __half* __restrict__ Ch, __half* __restrict__ Cl,
    int Mfixed, int N, int K,
    const int* __restrict__ offsets, const int* __restrict__ rowinfo,
    const float* __restrict__ bias,
    const float* __restrict__ bng, const float* __restrict__ bnb,
    const float* __restrict__ bnm, const float* __restrict__ bnv)
{
    extern __shared__ __align__(16) char sm[];
    int m0 = 0, M = Mfixed;
    if (SEG) {
        int e = blockIdx.z;
        m0 = offsets[e];
        M  = offsets[e + 1] - m0;
        Bp += (size_t)e * K * N;
        bias += (size_t)e * N;
        if (BN) { bng += (size_t)e * N; bnb += (size_t)e * N;
                  bnm += (size_t)e * N; bnv += (size_t)e * N; }
    }
    const int mtile = blockIdx.x * 128;
    if (mtile >= M) return;
    const int ntile = blockIdx.y * 128;

    const int tid = threadIdx.x, lane = tid & 31, wid = tid >> 5;
    const int warpM = wid & 3, warpN = wid >> 2;
    const uint32_t smBase = smem_u32(sm);

    // A fill: 4 rows/thread, 8B (4 fp16) per plane per row
    const int acg = tid & 7;
    const __half* aPh[4]; const __half* aPl[4];
    bool aval[4]; uint32_t aDst[4];
#pragma unroll
    for (int i = 0; i < 4; i++) {
        int row = (tid >> 3) + i * 32;
        bool v = (mtile + row) < M;
        aval[i] = v;
        int tok = 0;
        if (v) { int gr = m0 + mtile + row; tok = GATHER ? (rowinfo[gr] >> 2) : gr; }
        size_t off = (size_t)tok * K + acg * 4;
        aPh[i] = Ahp + off; aPl[i] = Alp + off;
        aDst[i] = (uint32_t)(row * 80 + acg * 8);
    }
    // B fill: single plane, 128 rows x 4 groups of 16B -> 512 uint4, 2/thread
    const __half* bPtr[2]; uint32_t bDst[2];
#pragma unroll
    for (int i = 0; i < 2; i++) {
        int idx = tid + (i << 8);
        int row = idx >> 2, cg = idx & 3;
        bPtr[i] = Bp + (size_t)(ntile + row) * K + cg * 8;
        bDst[i] = 20480u + (uint32_t)(row * 80 + cg * 16);
    }

    const int qa = lane >> 3, ra = lane & 7;
    const int lrow = ((qa & 1) << 3) + ra;
    const int lcolB = ((qa >> 1) << 3) * 2;
    const uint32_t aFragOff = (uint32_t)((warpM * 32 + lrow) * 80) + lcolB;
    const uint32_t bFragOff = (uint32_t)((warpN * 64 + lrow) * 80) + lcolB + 20480u;

    float acc[2][8][4];
#pragma unroll
    for (int mt = 0; mt < 2; mt++)
#pragma unroll
        for (int nt = 0; nt < 8; nt++)
#pragma unroll
            for (int q = 0; q < 4; q++) acc[mt][nt][q] = 0.0f;

    const int NC = K >> 5;
    const uint2 z2 = make_uint2(0u, 0u);

    // preload chunk 0
    {
        char* base = sm;
#pragma unroll
        for (int i = 0; i < 4; i++) {
            *(uint2*)(base + aDst[i])         = aval[i] ? *(const uint2*)aPh[i] : z2;
            *(uint2*)(base + 10240 + aDst[i]) = aval[i] ? *(const uint2*)aPl[i] : z2;
        }
#pragma unroll
        for (int i = 0; i < 2; i++)
            *(uint4*)(base + bDst[i]) = *(const uint4*)bPtr[i];
    }
    __syncthreads();

    for (int c = 0; c < NC; c++) {
        uint2 aRh[4], aRl[4]; uint4 bR[2];
        const bool pf = (c + 1) < NC;
        if (pf) {
            const int kc = (c + 1) << 5;
#pragma unroll
            for (int i = 0; i < 4; i++) {
                aRh[i] = aval[i] ? *(const uint2*)(aPh[i] + kc) : z2;
                aRl[i] = aval[i] ? *(const uint2*)(aPl[i] + kc) : z2;
            }
#pragma unroll
            for (int i = 0; i < 2; i++)
                bR[i] = *(const uint4*)(bPtr[i] + kc);
        }
        const uint32_t bb = smBase + (uint32_t)(c & 1) * 30720u;
#pragma unroll
        for (int ks = 0; ks < 2; ks++) {
            const uint32_t kso = ks * 32;
            uint4 ah[2], al[2];
#pragma unroll
            for (int mt = 0; mt < 2; mt++) {
                uint32_t ao = bb + aFragOff + mt * 1280u + kso;
                ah[mt] = ldm4(ao);
                al[mt] = ldm4(ao + 10240u);
            }
            uint32_t bf[8][2];
#pragma unroll
            for (int np = 0; np < 4; np++) {
                uint4 h = ldm4(bb + bFragOff + np * 1280u + kso);
                bf[2*np][0] = h.x; bf[2*np][1] = h.z;
                bf[2*np+1][0] = h.y; bf[2*np+1][1] = h.w;
            }
#pragma unroll
            for (int mt = 0; mt < 2; mt++)
#pragma unroll
                for (int nt = 0; nt < 8; nt++) {
                    mma_fp16(acc[mt][nt], ah[mt], bf[nt][0], bf[nt][1]);
                    mma_fp16(acc[mt][nt], al[mt], bf[nt][0], bf[nt][1]);
                }
        }
        if (pf) {
            char* base = sm + ((c + 1) & 1) * 30720;
#pragma unroll
            for (int i = 0; i < 4; i++) {
                *(uint2*)(base + aDst[i])         = aRh[i];
                *(uint2*)(base + 10240 + aDst[i]) = aRl[i];
            }
#pragma unroll
            for (int i = 0; i < 2; i++)
                *(uint4*)(base + bDst[i]) = bR[i];
        }
        __syncthreads();
    }

    // epilogue: bias (+BN+GELU); output fp32 or split fp16 planes
    const int g = lane >> 2, tt = lane & 3;
#pragma unroll
    for (int mt = 0; mt < 2; mt++) {
#pragma unroll
        for (int half = 0; half < 2; half++) {
            int rl = mtile + warpM * 32 + mt * 16 + half * 8 + g;
            if (rl < M) {
                int gr = m0 + rl;
                int crow = SCATTER ? rowinfo[gr] : gr;
                size_t rowoff = (size_t)crow * N;
#pragma unroll
                for (int nt = 0; nt < 8; nt++) {
                    int cn = ntile + warpN * 64 + nt * 8 + tt * 2;
                    float x0 = acc[mt][nt][half * 2 + 0] + __ldg(bias + cn);
                    float x1 = acc[mt][nt][half * 2 + 1] + __ldg(bias + cn + 1);
                    if (BN) {
                        x0 = gelu_f((x0 - __ldg(bnm + cn)) * rsqrtf(__ldg(bnv + cn) + EPSN)
                                    * __ldg(bng + cn) + __ldg(bnb + cn));
                        x1 = gelu_f((x1 - __ldg(bnm + cn + 1)) * rsqrtf(__ldg(bnv + cn + 1) + EPSN)
                                    * __ldg(bng + cn + 1) + __ldg(bnb + cn + 1));
                    }
                    if (OUTS) {
                        __half h0, l0, h1v, l1v;
                        split2h(x0, h0, l0); split2h(x1, h1v, l1v);
                        *(uint32_t*)(Ch + rowoff + cn) = pkh(h0, h1v);
                        *(uint32_t*)(Cl + rowoff + cn) = pkh(l0, l1v);
                    } else {
                        *(float2*)(C + rowoff + cn) = make_float2(x0, x1);
                    }
                }
            }
        }
    }
}

// ---- fp32 gate GEMM (selection-exact): [4096,512]@[512,1024]+b ----
__global__ void __launch_bounds__(256, 2) gate_gemm(
    const float* __restrict__ A, const float* __restrict__ Bw,
    float* __restrict__ C, const float* __restrict__ bias)
{
    const int N = HDIM, K = DIN;
    const int mtile = blockIdx.x * 128, ntile = blockIdx.y * 128;
    __shared__ float As[16][128], Bs[16][128];
    const int tid = threadIdx.x, tx = tid & 15, ty = tid >> 4;
    const int arow0 = tid >> 2, arow1 = arow0 + 64, ak4 = (tid & 3) << 2;
    const size_t ab0 = (size_t)(mtile + arow0) * K, ab1 = (size_t)(mtile + arow1) * K;
    const int brow = tid >> 5, bc4 = (tid & 31) << 2;
    float acc[8][8];
#pragma unroll
    for (int i = 0; i < 8; i++)
#pragma unroll
        for (int j = 0; j < 8; j++) acc[i][j] = 0.0f;
    for (int kt = 0; kt < K; kt += 16) {
        float4 a0 = *(const float4*)(A + ab0 + kt + ak4);
        float4 a1 = *(const float4*)(A + ab1 + kt + ak4);
        As[ak4 + 0][arow0] = a0.x; As[ak4 + 1][arow0] = a0.y;
        As[ak4 + 2][arow0] = a0.z; As[ak4 + 3][arow0] = a0.w;
        As[ak4 + 0][arow1] = a1.x; As[ak4 + 1][arow1] = a1.y;
        As[ak4 + 2][arow1] = a1.z; As[ak4 + 3][arow1] = a1.w;
        *(float4*)&Bs[brow    ][bc4] = *(const float4*)(Bw + (size_t)(kt + brow    ) * N + ntile + bc4);
        *(float4*)&Bs[brow + 8][bc4] = *(const float4*)(Bw + (size_t)(kt + brow + 8) * N + ntile + bc4);
        __syncthreads();
#pragma unroll
        for (int k = 0; k < 16; k++) {
            float af[8], bf[8];
            *(float4*)&af[0] = *(float4*)&As[k][ty * 8];
            *(float4*)&af[4] = *(float4*)&As[k][ty * 8 + 4];
            *(float4*)&bf[0] = *(float4*)&Bs[k][tx * 8];
            *(float4*)&bf[4] = *(float4*)&Bs[k][tx * 8 + 4];
#pragma unroll
            for (int i = 0; i < 8; i++)
#pragma unroll
                for (int j = 0; j < 8; j++) acc[i][j] += af[i] * bf[j];
        }
        __syncthreads();
    }
    const int cn = ntile + tx * 8;
    float bi[8];
    *(float4*)&bi[0] = *(const float4*)(bias + cn);
    *(float4*)&bi[4] = *(const float4*)(bias + cn + 4);
#pragma unroll
    for (int i = 0; i < 8; i++) {
        float v[8];
#pragma unroll
        for (int j = 0; j < 8; j++) v[j] = acc[i][j] + bi[j];
        float* cp = C + (size_t)(mtile + ty * 8 + i) * N + cn;
        *(float4*)cp = *(float4*)&v[0];
        *(float4*)(cp + 4) = *(float4*)&v[4];
    }
}

// ---- LayerNorm + GELU (in place, row=1024) ----
__global__ void ln_gelu_kernel(float* __restrict__ x, const float* __restrict__ g,
                               const float* __restrict__ b) {
    int row = blockIdx.x;
    float* xr = x + (size_t)row * HDIM;
    int t = threadIdx.x;
    float4 v = *(float4*)&xr[t * 4];
    float s = v.x + v.y + v.z + v.w;
    float q = v.x * v.x + v.y * v.y + v.z * v.z + v.w * v.w;
#pragma unroll
    for (int o = 16; o; o >>= 1) {
        s += __shfl_down_sync(0xffffffffu, s, o);
        q += __shfl_down_sync(0xffffffffu, q, o);
    }
    __shared__ float ss[8], qq[8];
    int w = t >> 5, l = t & 31;
    if (l == 0) { ss[w] = s; qq[w] = q; }
    __syncthreads();
    if (w == 0) {
        s = (l < 8) ? ss[l] : 0.0f;
        q = (l < 8) ? qq[l] : 0.0f;
#pragma unroll
        for (int o = 4; o; o >>= 1) {
            s += __shfl_down_sync(0xffffffffu, s, o);
            q += __shfl_down_sync(0xffffffffu, q, o);
        }
        if (l == 0) { ss[0] = s; qq[0] = q; }
    }
    __syncthreads();
    float mu  = ss[0] * (1.0f / HDIM);
    float var = qq[0] * (1.0f / HDIM) - mu * mu;
    float r = rsqrtf(var + EPSN);
    float4 gv = *(const float4*)&g[t * 4];
    float4 bv = *(const float4*)&b[t * 4];
    v.x = gelu_f((v.x - mu) * r * gv.x + bv.x);
    v.y = gelu_f((v.y - mu) * r * gv.y + bv.y);
    v.z = gelu_f((v.z - mu) * r * gv.z + bv.z);
    v.w = gelu_f((v.w - mu) * r * gv.w + bv.w);
    *(float4*)&xr[t * 4] = v;
}

// ---- gate logits + softmax + top4 + renorm ----
__global__ void gate_topk_kernel(const float* __restrict__ g1, const float* __restrict__ w2,
                                 const float* __restrict__ b2, int* __restrict__ tidx,
                                 float* __restrict__ tw, int* __restrict__ counts) {
    int b = blockIdx.x, t = threadIdx.x;
    int e = t >> 3, sub = t & 7;
    const float* row = g1 + (size_t)b * HDIM;
    float s = 0.0f;
    for (int k = sub; k < HDIM; k += 8) s += row[k] * w2[k * NEXP + e];
    s += __shfl_down_sync(0xffffffffu, s, 4);
    s += __shfl_down_sync(0xffffffffu, s, 2);
    s += __shfl_down_sync(0xffffffffu, s, 1);
    __shared__ float logit[NEXP];
    if (sub == 0) logit[e] = s + b2[e];
    __syncthreads();
    if (t == 0) {
        float mx = -1e30f;
        for (int i = 0; i < NEXP; i++) mx = fmaxf(mx, logit[i]);
        float p[NEXP], sum = 0.0f;
        for (int i = 0; i < NEXP; i++) { p[i] = expf(logit[i] - mx); sum += p[i]; }
        float inv = 1.0f / sum;
        bool used[NEXP];
        for (int i = 0; i < NEXP; i++) used[i] = false;
        int idx[KSEL]; float val[KSEL];
        for (int tk = 0; tk < KSEL; tk++) {
            int best = -1; float bv = -1e30f;
            for (int i = 0; i < NEXP; i++)
                if (!used[i] && p[i] > bv) { bv = p[i]; best = i; }
            used[best] = true; idx[tk] = best; val[tk] = bv * inv;
        }
        float m2 = val[0], e2[KSEL], s2 = 0.0f;
        for (int tk = 0; tk < KSEL; tk++) { e2[tk] = expf(val[tk] - m2); s2 += e2[tk]; }
        float inv2 = 1.0f / s2;
        for (int tk = 0; tk < KSEL; tk++) {
            tidx[b * KSEL + tk] = idx[tk];
            tw[b * KSEL + tk]   = e2[tk] * inv2;
            atomicAdd(&counts[idx[tk]], 1);
        }
    }
}

// ---- dispatch bookkeeping ----
__global__ void reset_kernel(int* __restrict__ counts) {
    if (threadIdx.x < NEXP) counts[threadIdx.x] = 0;
}
__global__ void scan_kernel(const int* __restrict__ counts, int* __restrict__ offsets,
                            int* __restrict__ cursor) {
    if (threadIdx.x == 0) {
        int acc = 0;
        for (int e = 0; e < NEXP; e++) { offsets[e] = acc; cursor[e] = acc; acc += counts[e]; }
        offsets[NEXP] = acc;
    }
}
__global__ void scatter_kernel(const int* __restrict__ tidx, int* __restrict__ cursor,
                               int* __restrict__ rowinfo) {
    int i = blockIdx.x * 256 + threadIdx.x;
    if (i < BTOK * KSEL) {
        int pos = atomicAdd(&cursor[tidx[i]], 1);
        rowinfo[pos] = i;
    }
}

// ---- weighted top-k combine -> pre-split fp16 planes ----
__global__ void combine_kernel(const float* __restrict__ h2, const float* __restrict__ tw,
                               __half* __restrict__ fh, __half* __restrict__ fl) {
    int idx = blockIdx.x * 256 + threadIdx.x;
    if (idx < BTOK * HDIM) {
        int b = idx >> 10, h = idx & (HDIM - 1);
        const float* base = h2 + ((size_t)b * KSEL) * HDIM + h;
        const float* w = tw + b * KSEL;
        float v = w[0] * base[0] + w[1] * base[HDIM]
                + w[2] * base[2 * HDIM] + w[3] * base[3 * HDIM];
        __half hh, ll; split2h(v, hh, ll);
        fh[idx] = hh; fl[idx] = ll;
    }
}

// ---- final head GEMM [4096,512]x[512,20] ----
__global__ void final_kernel(const float* __restrict__ o1, const float* __restrict__ w2,
                             const float* __restrict__ b2, float* __restrict__ out) {
    int b = blockIdx.x;
    __shared__ float row[512];
    int t = threadIdx.x;
    for (int k = t; k < 512; k += 160) row[k] = o1[(size_t)b * 512 + k];
    __syncthreads();
    int c = t >> 3, sub = t & 7;
    float s = 0.0f;
    for (int k = sub; k < 512; k += 8) s += row[k] * w2[k * NCLS + c];
    s += __shfl_down_sync(0xffffffffu, s, 4);
    s += __shfl_down_sync(0xffffffffu, s, 2);
    s += __shfl_down_sync(0xffffffffu, s, 1);
    if (sub == 0) out[b * NCLS + c] = s + b2[c];
}

// ---- launch ----
extern "C" void kernel_launch(void* const* d_in, const int* in_sizes, int n_in,
                              void* d_out, int out_size) {
    const float* wifi      = (const float*)d_in[0];
    const float* rfid      = (const float*)d_in[1];
    const float* gate_w1   = (const float*)d_in[2];
    const float* gate_b1   = (const float*)d_in[3];
    const float* gate_ln_g = (const float*)d_in[4];
    const float* gate_ln_b = (const float*)d_in[5];
    const float* gate_w2   = (const float*)d_in[6];
    const float* gate_b2   = (const float*)d_in[7];
    const float* exp_w1    = (const float*)d_in[8];
    const float* exp_b1    = (const float*)d_in[9];
    const float* exp_bn1_g = (const float*)d_in[10];
    const float* exp_bn1_b = (const float*)d_in[11];
    const float* exp_bn1_m = (const float*)d_in[12];
    const float* exp_bn1_v = (const float*)d_in[13];
    const float* exp_w2    = (const float*)d_in[14];
    const float* exp_b2    = (const float*)d_in[15];
    const float* exp_bn2_g = (const float*)d_in[16];
    const float* exp_bn2_b = (const float*)d_in[17];
    const float* exp_bn2_m = (const float*)d_in[18];
    const float* exp_bn2_v = (const float*)d_in[19];
    const float* fin_w1    = (const float*)d_in[20];
    const float* fin_b1    = (const float*)d_in[21];
    const float* fin_bn_g  = (const float*)d_in[22];
    const float* fin_bn_b  = (const float*)d_in[23];
    const float* fin_bn_m  = (const float*)d_in[24];
    const float* fin_bn_v  = (const float*)d_in[25];
    const float* fin_w2    = (const float*)d_in[26];
    const float* fin_b2    = (const float*)d_in[27];
    float* out = (float*)d_out;

    float *combined, *g1, *tw, *h2, *o1;
    int *tidx, *counts, *cursor, *offsets, *rowinfo;
    __half *combh, *combl, *h1h, *h1l, *fusedh, *fusedl;
    __half *ew1f, *ew2f, *fw1f;
    cudaGetSymbolAddress((void**)&combined, g_combined);
    cudaGetSymbolAddress((void**)&combh,    g_combh);
    cudaGetSymbolAddress((void**)&combl,    g_combl);
    cudaGetSymbolAddress((void**)&g1,       g_g1);
    cudaGetSymbolAddress((void**)&tidx,     g_tidx);
    cudaGetSymbolAddress((void**)&tw,       g_tw);
    cudaGetSymbolAddress((void**)&counts,   g_counts);
    cudaGetSymbolAddress((void**)&cursor,   g_cursor);
    cudaGetSymbolAddress((void**)&offsets,  g_offsets);
    cudaGetSymbolAddress((void**)&rowinfo,  g_rowinfo);
    cudaGetSymbolAddress((void**)&h1h,      g_h1h);
    cudaGetSymbolAddress((void**)&h1l,      g_h1l);
    cudaGetSymbolAddress((void**)&h2,       g_h2);
    cudaGetSymbolAddress((void**)&fusedh,   g_fusedh);
    cudaGetSymbolAddress((void**)&fusedl,   g_fusedl);
    cudaGetSymbolAddress((void**)&o1,       g_o1);
    cudaGetSymbolAddress((void**)&ew1f,     g_ew1f);
    cudaGetSymbolAddress((void**)&ew2f,     g_ew2f);
    cudaGetSymbolAddress((void**)&fw1f,     g_fw1f);

    cudaFuncSetAttribute(w_gemm<true, true, false, true, true>,
                         cudaFuncAttributeMaxDynamicSharedMemorySize, WG_SMEM);
    cudaFuncSetAttribute(w_gemm<true, false, true, true, false>,
                         cudaFuncAttributeMaxDynamicSharedMemorySize, WG_SMEM);
    cudaFuncSetAttribute(w_gemm<false, false, false, true, false>,
                         cudaFuncAttributeMaxDynamicSharedMemorySize, WG_SMEM);

    // weight transpose+convert (pure bandwidth)
    wsplit_kernel<<<dim3(32, 16, NEXP), dim3(32, 8)>>>(exp_w1, ew1f, DIN, HDIM);
    wsplit_kernel<<<dim3(32, 32, NEXP), dim3(32, 8)>>>(exp_w2, ew2f, HDIM, HDIM);
    wsplit_kernel<<<dim3(16, 32, 1),    dim3(32, 8)>>>(fin_w1, fw1f, HDIM, 512);

    // 1. concat (fp32 + pre-split fp16 planes)
    concat_kernel<<<(BTOK * DIN + 255) / 256, 256>>>(wifi, rfid, combined, combh, combl);
    // 2. gate GEMM1 (exact fp32)
    gate_gemm<<<dim3(32, 8), 256>>>(combined, gate_w1, g1, gate_b1);
    // 3. LN + GELU
    ln_gelu_kernel<<<BTOK, 256>>>(g1, gate_ln_g, gate_ln_b);
    // 4. gate top-4
    reset_kernel<<<1, 32>>>(counts);
    gate_topk_kernel<<<BTOK, 128>>>(g1, gate_w2, gate_b2, tidx, tw, counts);
    // 5. dispatch
    scan_kernel<<<1, 1>>>(counts, offsets, cursor);
    scatter_kernel<<<(BTOK * KSEL + 255) / 256, 256>>>(tidx, cursor, rowinfo);
    // 6. expert GEMM1 (gather, BN1+GELU, fp16-split output)
    w_gemm<true, true, false, true, true><<<dim3(32, 8, NEXP), 256, WG_SMEM>>>(
        combh, combl, ew1f, nullptr, h1h, h1l, 0, HDIM, DIN,
        offsets, rowinfo, exp_b1, exp_bn1_g, exp_bn1_b, exp_bn1_m, exp_bn1_v);
    // 7. expert GEMM2 (scatter, BN2+GELU, fp32 output)
    w_gemm<true, false, true, true, false><<<dim3(32, 8, NEXP), 256, WG_SMEM>>>(
        h1h, h1l, ew2f, h2, nullptr, nullptr, 0, HDIM, HDIM,
        offsets, rowinfo, exp_b2, exp_bn2_g, exp_bn2_b, exp_bn2_m, exp_bn2_v);
    // 8. combine -> pre-split fp16 planes
    combine_kernel<<<(BTOK * HDIM + 255) / 256, 256>>>(h2, tw, fusedh, fusedl);
    // 9. final GEMM1 (BN+GELU, fp32 output)
    w_gemm<false, false, false, true, false><<<dim3(32, 4, 1), 256, WG_SMEM>>>(
        fusedh, fusedl, fw1f, o1, nullptr, nullptr, BTOK, 512, HDIM,
        nullptr, nullptr, fin_b1, fin_bn_g, fin_bn_b, fin_bn_m, fin_bn_v);
    // 10. head
    final_kernel<<<BTOK, 160>>>(o1, fin_w2, fin_b2, out);
}

// round 11
// speedup vs baseline: 2.6104x; 1.2356x over previous
#include <cuda_runtime.h>
#include <cuda_fp16.h>
#include <math.h>
#include <stdint.h>

#define BTOK 4096
#define DIN  512
#define HDIM 1024
#define NEXP 16
#define KSEL 4
#define NCLS 20
#define EPSN 1e-5f

// ---- device scratch (no allocation allowed) ----
__device__ float  g_combined[BTOK * DIN];       // fp32 (gate path)
__device__ __half g_combf[BTOK * DIN];          // fp16 A for GEMM1
__device__ float  g_g1[BTOK * HDIM];
__device__ int    g_tidx[BTOK * KSEL];
__device__ float  g_tw[BTOK * KSEL];
__device__ int    g_counts[NEXP];
__device__ int    g_cursor[NEXP];
__device__ int    g_offsets[NEXP + 1];
__device__ int    g_rowinfo[BTOK * KSEL];
__device__ __half g_h1f[BTOK * KSEL * HDIM];    // GEMM1 out (GEMM2 A)
__device__ float  g_h2[BTOK * KSEL * HDIM];
__device__ __half g_fusedf[BTOK * HDIM];        // combine out (final A)
__device__ float  g_o1[BTOK * 512];
__device__ __half g_ew1f[NEXP * DIN * HDIM];    // fp16 weights [N,K]
__device__ __half g_ew2f[NEXP * HDIM * HDIM];
__device__ __half g_fw1f[HDIM * 512];

__device__ __forceinline__ float gelu_f(float x) {
    return 0.5f * x * (1.0f + erff(x * 0.70710678118654752440f));
}
__device__ __forceinline__ uint32_t smem_u32(const void* p) {
    uint32_t a;
    asm("{ .reg .u64 t; cvta.to.shared.u64 t, %1; cvt.u32.u64 %0, t; }" : "=r"(a) : "l"(p));
    return a;
}
__device__ __forceinline__ uint4 ldm4(uint32_t addr) {
    uint4 r;
    asm volatile("ldmatrix.sync.aligned.m8n8.x4.shared.b16 {%0,%1,%2,%3}, [%4];"
                 : "=r"(r.x), "=r"(r.y), "=r"(r.z), "=r"(r.w) : "r"(addr));
    return r;
}
__device__ __forceinline__ void mma_fp16(float* c, const uint4& a, uint32_t b0, uint32_t b1) {
    asm volatile(
        "mma.sync.aligned.m16n8k16.row.col.f32.f16.f16.f32 "
        "{%0,%1,%2,%3}, {%4,%5,%6,%7}, {%8,%9}, {%0,%1,%2,%3};"
        : "+f"(c[0]), "+f"(c[1]), "+f"(c[2]), "+f"(c[3])
        : "r"(a.x), "r"(a.y), "r"(a.z), "r"(a.w), "r"(b0), "r"(b1));
}
__device__ __forceinline__ uint32_t pkh(__half a, __half b) {
    return (uint32_t)__half_as_ushort(a) | ((uint32_t)__half_as_ushort(b) << 16);
}

// ---- concat: fp32 (gate) + fp16 plane ----
__global__ void concat_kernel(const float* __restrict__ wifi, const float* __restrict__ rfid,
                              float* __restrict__ comb, __half* __restrict__ cf) {
    int i = blockIdx.x * 256 + threadIdx.x;
    if (i < BTOK * DIN) {
        int b = i >> 9, c = i & 511;
        float v = (c < 256) ? wifi[b * 256 + c] : rfid[b * 256 + (c - 256)];
        comb[i] = v;
        cf[i] = __float2half_rn(v);
    }
}

// ---- weight transpose + fp16 convert: W[e,K,N] -> T[e,N,K] ----
__global__ void wsplit_kernel(const float* __restrict__ W, __half* __restrict__ Tf,
                              int K, int N) {
    __shared__ float tile[32][33];
    size_t base = (size_t)blockIdx.z * K * N;
    int k0 = blockIdx.y * 32, n0 = blockIdx.x * 32;
    int tx = threadIdx.x, ty = threadIdx.y;
#pragma unroll
    for (int i = 0; i < 32; i += 8)
        tile[ty + i][tx] = W[base + (size_t)(k0 + ty + i) * N + n0 + tx];
    __syncthreads();
#pragma unroll
    for (int i = 0; i < 32; i += 8) {
        int n = n0 + ty + i, k = k0 + tx;
        Tf[base + (size_t)n * K + k] = __float2half_rn(tile[tx][ty + i]);
    }
}

// ---------------------------------------------------------------------------
// fp16 1-pass HMMA GEMM: C = A @ B, fp32 accumulate.
// A: fp16 [M,K] row-major. B: fp16 [N,K] (pre-transposed).
// CTA 128x128, 256 thr (8 warps 4Mx2N), k-chunk 32, double-buffered SMEM,
// 80B padded rows (conflict-free ldmatrix).
// SMEM buffer layout: A@0 (10240), B@10240 (10240) -> 20480/buffer.
// ---------------------------------------------------------------------------
static constexpr int WG_SMEM = 2 * 20480;

template<bool SEG, bool GATHER, bool SCATTER, bool BN, bool OUTS>
__global__ void __launch_bounds__(256, 1) w_gemm(
    const __half* __restrict__ Ap, const __half* __restrict__ Bp,
    float* __restrict__ C, __half* __restrict__ Cf,
    int Mfixed, int N, int K,
    const int* __restrict__ offsets, const int* __restrict__ rowinfo,
    const float* __restrict__ bias,
    const float* __restrict__ bng, const float* __restrict__ bnb,
    const float* __restrict__ bnm, const float* __restrict__ bnv)
{
    extern __shared__ __align__(16) char sm[];
    int m0 = 0, M = Mfixed;
    if (SEG) {
        int e = blockIdx.z;
        m0 = offsets[e];
        M  = offsets[e + 1] - m0;
        Bp += (size_t)e * K * N;
        bias += (size_t)e * N;
        if (BN) { bng += (size_t)e * N; bnb += (size_t)e * N;
                  bnm += (size_t)e * N; bnv += (size_t)e * N; }
    }
    const int mtile = blockIdx.x * 128;
    if (mtile >= M) return;
    const int ntile = blockIdx.y * 128;

    const int tid = threadIdx.x, lane = tid & 31, wid = tid >> 5;
    const int warpM = wid & 3, warpN = wid >> 2;
    const uint32_t smBase = smem_u32(sm);

    // A fill: 4 rows/thread, 8B (4 fp16) per row
    const int acg = tid & 7;
    const __half* aP[4]; bool aval[4]; uint32_t aDst[4];
#pragma unroll
    for (int i = 0; i < 4; i++) {
        int row = (tid >> 3) + i * 32;
        bool v = (mtile + row) < M;
        aval[i] = v;
        int tok = 0;
        if (v) { int gr = m0 + mtile + row; tok = GATHER ? (rowinfo[gr] >> 2) : gr; }
        aP[i] = Ap + (size_t)tok * K + acg * 4;
        aDst[i] = (uint32_t)(row * 80 + acg * 8);
    }
    // B fill: 128 rows x 4 groups of 16B -> 512 uint4, 2/thread
    const __half* bPtr[2]; uint32_t bDst[2];
#pragma unroll
    for (int i = 0; i < 2; i++) {
        int idx = tid + (i << 8);
        int row = idx >> 2, cg = idx & 3;
        bPtr[i] = Bp + (size_t)(ntile + row) * K + cg * 8;
        bDst[i] = 10240u + (uint32_t)(row * 80 + cg * 16);
    }

    const int qa = lane >> 3, ra = lane & 7;
    const int lrow = ((qa & 1) << 3) + ra;
    const int lcolB = ((qa >> 1) << 3) * 2;
    const uint32_t aFragOff = (uint32_t)((warpM * 32 + lrow) * 80) + lcolB;
    const uint32_t bFragOff = (uint32_t)((warpN * 64 + lrow) * 80) + lcolB + 10240u;

    float acc[2][8][4];
#pragma unroll
    for (int mt = 0; mt < 2; mt++)
#pragma unroll
        for (int nt = 0; nt < 8; nt++)
#pragma unroll
            for (int q = 0; q < 4; q++) acc[mt][nt][q] = 0.0f;

    const int NC = K >> 5;
    const uint2 z2 = make_uint2(0u, 0u);

    // preload chunk 0
    {
        char* base = sm;
#pragma unroll
        for (int i = 0; i < 4; i++)
            *(uint2*)(base + aDst[i]) = aval[i] ? *(const uint2*)aP[i] : z2;
#pragma unroll
        for (int i = 0; i < 2; i++)
            *(uint4*)(base + bDst[i]) = *(const uint4*)bPtr[i];
    }
    __syncthreads();

    for (int c = 0; c < NC; c++) {
        uint2 aR[4]; uint4 bR[2];
        const bool pf = (c + 1) < NC;
        if (pf) {
            const int kc = (c + 1) << 5;
#pragma unroll
            for (int i = 0; i < 4; i++)
                aR[i] = aval[i] ? *(const uint2*)(aP[i] + kc) : z2;
#pragma unroll
            for (int i = 0; i < 2; i++)
                bR[i] = *(const uint4*)(bPtr[i] + kc);
        }
        const uint32_t bb = smBase + (uint32_t)(c & 1) * 20480u;
#pragma unroll
        for (int ks = 0; ks < 2; ks++) {
            const uint32_t kso = ks * 32;
            uint4 ah[2];
#pragma unroll
            for (int mt = 0; mt < 2; mt++)
                ah[mt] = ldm4(bb + aFragOff + mt * 1280u + kso);
            uint32_t bf[8][2];
#pragma unroll
            for (int np = 0; np < 4; np++) {
                uint4 h = ldm4(bb + bFragOff + np * 1280u + kso);
                bf[2*np][0] = h.x; bf[2*np][1] = h.z;
                bf[2*np+1][0] = h.y; bf[2*np+1][1] = h.w;
            }
#pragma unroll
            for (int mt = 0; mt < 2; mt++)
#pragma unroll
                for (int nt = 0; nt < 8; nt++)
                    mma_fp16(acc[mt][nt], ah[mt], bf[nt][0], bf[nt][1]);
        }
        if (pf) {
            char* base = sm + ((c + 1) & 1) * 20480;
#pragma unroll
            for (int i = 0; i < 4; i++)
                *(uint2*)(base + aDst[i]) = aR[i];
#pragma unroll
            for (int i = 0; i < 2; i++)
                *(uint4*)(base + bDst[i]) = bR[i];
        }
        __syncthreads();
    }

    // epilogue: bias (+BN+GELU); output fp32 or fp16 plane
    const int g = lane >> 2, tt = lane & 3;
#pragma unroll
    for (int mt = 0; mt < 2; mt++) {
#pragma unroll
        for (int half = 0; half < 2; half++) {
            int rl = mtile + warpM * 32 + mt * 16 + half * 8 + g;
            if (rl < M) {
                int gr = m0 + rl;
                int crow = SCATTER ? rowinfo[gr] : gr;
                size_t rowoff = (size_t)crow * N;
#pragma unroll
                for (int nt = 0; nt < 8; nt++) {
                    int cn = ntile + warpN * 64 + nt * 8 + tt * 2;
                    float x0 = acc[mt][nt][half * 2 + 0] + __ldg(bias + cn);
                    float x1 = acc[mt][nt][half * 2 + 1] + __ldg(bias + cn + 1);
                    if (BN) {
                        x0 = gelu_f((x0 - __ldg(bnm + cn)) * rsqrtf(__ldg(bnv + cn) + EPSN)
                                    * __ldg(bng + cn) + __ldg(bnb + cn));
                        x1 = gelu_f((x1 - __ldg(bnm + cn + 1)) * rsqrtf(__ldg(bnv + cn + 1) + EPSN)
                                    * __ldg(bng + cn + 1) + __ldg(bnb + cn + 1));
                    }
                    if (OUTS) {
                        *(uint32_t*)(Cf + rowoff + cn) =
                            pkh(__float2half_rn(x0), __float2half_rn(x1));
                    } else {
                        *(float2*)(C + rowoff + cn) = make_float2(x0, x1);
                    }
                }
            }
        }
    }
}

// ---- fp32 gate GEMM (selection-exact): [4096,512]@[512,1024]+b ----
__global__ void __launch_bounds__(256, 2) gate_gemm(
    const float* __restrict__ A, const float* __restrict__ Bw,
    float* __restrict__ C, const float* __restrict__ bias)
{
    const int N = HDIM, K = DIN;
    const int mtile = blockIdx.x * 128, ntile = blockIdx.y * 128;
    __shared__ float As[16][128], Bs[16][128];
    const int tid = threadIdx.x, tx = tid & 15, ty = tid >> 4;
    const int arow0 = tid >> 2, arow1 = arow0 + 64, ak4 = (tid & 3) << 2;
    const size_t ab0 = (size_t)(mtile + arow0) * K, ab1 = (size_t)(mtile + arow1) * K;
    const int brow = tid >> 5, bc4 = (tid & 31) << 2;
    float acc[8][8];
#pragma unroll
    for (int i = 0; i < 8; i++)
#pragma unroll
        for (int j = 0; j < 8; j++) acc[i][j] = 0.0f;
    for (int kt = 0; kt < K; kt += 16) {
        float4 a0 = *(const float4*)(A + ab0 + kt + ak4);
        float4 a1 = *(const float4*)(A + ab1 + kt + ak4);
        As[ak4 + 0][arow0] = a0.x; As[ak4 + 1][arow0] = a0.y;
        As[ak4 + 2][arow0] = a0.z; As[ak4 + 3][arow0] = a0.w;
        As[ak4 + 0][arow1] = a1.x; As[ak4 + 1][arow1] = a1.y;
        As[ak4 + 2][arow1] = a1.z; As[ak4 + 3][arow1] = a1.w;
        *(float4*)&Bs[brow    ][bc4] = *(const float4*)(Bw + (size_t)(kt + brow    ) * N + ntile + bc4);
        *(float4*)&Bs[brow + 8][bc4] = *(const float4*)(Bw + (size_t)(kt + brow + 8) * N + ntile + bc4);
        __syncthreads();
#pragma unroll
        for (int k = 0; k < 16; k++) {
            float af[8], bf[8];
            *(float4*)&af[0] = *(float4*)&As[k][ty * 8];
            *(float4*)&af[4] = *(float4*)&As[k][ty * 8 + 4];
            *(float4*)&bf[0] = *(float4*)&Bs[k][tx * 8];
            *(float4*)&bf[4] = *(float4*)&Bs[k][tx * 8 + 4];
#pragma unroll
            for (int i = 0; i < 8; i++)
#pragma unroll
                for (int j = 0; j < 8; j++) acc[i][j] += af[i] * bf[j];
        }
        __syncthreads();
    }
    const int cn = ntile + tx * 8;
    float bi[8];
    *(float4*)&bi[0] = *(const float4*)(bias + cn);
    *(float4*)&bi[4] = *(const float4*)(bias + cn + 4);
#pragma unroll
    for (int i = 0; i < 8; i++) {
        float v[8];
#pragma unroll
        for (int j = 0; j < 8; j++) v[j] = acc[i][j] + bi[j];
        float* cp = C + (size_t)(mtile + ty * 8 + i) * N + cn;
        *(float4*)cp = *(float4*)&v[0];
        *(float4*)(cp + 4) = *(float4*)&v[4];
    }
}

// ---- LayerNorm + GELU (in place, row=1024) ----
__global__ void ln_gelu_kernel(float* __restrict__ x, const float* __restrict__ g,
                               const float* __restrict__ b) {
    int row = blockIdx.x;
    float* xr = x + (size_t)row * HDIM;
    int t = threadIdx.x;
    float4 v = *(float4*)&xr[t * 4];
    float s = v.x + v.y + v.z + v.w;
    float q = v.x * v.x + v.y * v.y + v.z * v.z + v.w * v.w;
#pragma unroll
    for (int o = 16; o; o >>= 1) {
        s += __shfl_down_sync(0xffffffffu, s, o);
        q += __shfl_down_sync(0xffffffffu, q, o);
    }
    __shared__ float ss[8], qq[8];
    int w = t >> 5, l = t & 31;
    if (l == 0) { ss[w] = s; qq[w] = q; }
    __syncthreads();
    if (w == 0) {
        s = (l < 8) ? ss[l] : 0.0f;
        q = (l < 8) ? qq[l] : 0.0f;
#pragma unroll
        for (int o = 4; o; o >>= 1) {
            s += __shfl_down_sync(0xffffffffu, s, o);
            q += __shfl_down_sync(0xffffffffu, q, o);
        }
        if (l == 0) { ss[0] = s; qq[0] = q; }
    }
    __syncthreads();
    float mu  = ss[0] * (1.0f / HDIM);
    float var = qq[0] * (1.0f / HDIM) - mu * mu;
    float r = rsqrtf(var + EPSN);
    float4 gv = *(const float4*)&g[t * 4];
    float4 bv = *(const float4*)&b[t * 4];
    v.x = gelu_f((v.x - mu) * r * gv.x + bv.x);
    v.y = gelu_f((v.y - mu) * r * gv.y + bv.y);
    v.z = gelu_f((v.z - mu) * r * gv.z + bv.z);
    v.w = gelu_f((v.w - mu) * r * gv.w + bv.w);
    *(float4*)&xr[t * 4] = v;
}

// ---- gate logits + softmax + top4 + renorm ----
__global__ void gate_topk_kernel(const float* __restrict__ g1, const float* __restrict__ w2,
                                 const float* __restrict__ b2, int* __restrict__ tidx,
                                 float* __restrict__ tw, int* __restrict__ counts) {
    int b = blockIdx.x, t = threadIdx.x;
    int e = t >> 3, sub = t & 7;
    const float* row = g1 + (size_t)b * HDIM;
    float s = 0.0f;
    for (int k = sub; k < HDIM; k += 8) s += row[k] * w2[k * NEXP + e];
    s += __shfl_down_sync(0xffffffffu, s, 4);
    s += __shfl_down_sync(0xffffffffu, s, 2);
    s += __shfl_down_sync(0xffffffffu, s, 1);
    __shared__ float logit[NEXP];
    if (sub == 0) logit[e] = s + b2[e];
    __syncthreads();
    if (t == 0) {
        float mx = -1e30f;
        for (int i = 0; i < NEXP; i++) mx = fmaxf(mx, logit[i]);
        float p[NEXP], sum = 0.0f;
        for (int i = 0; i < NEXP; i++) { p[i] = expf(logit[i] - mx); sum += p[i]; }
        float inv = 1.0f / sum;
        bool used[NEXP];
        for (int i = 0; i < NEXP; i++) used[i] = false;
        int idx[KSEL]; float val[KSEL];
        for (int tk = 0; tk < KSEL; tk++) {
            int best = -1; float bv = -1e30f;
            for (int i = 0; i < NEXP; i++)
                if (!used[i] && p[i] > bv) { bv = p[i]; best = i; }
            used[best] = true; idx[tk] = best; val[tk] = bv * inv;
        }
        float m2 = val[0], e2[KSEL], s2 = 0.0f;
        for (int tk = 0; tk < KSEL; tk++) { e2[tk] = expf(val[tk] - m2); s2 += e2[tk]; }
        float inv2 = 1.0f / s2;
        for (int tk = 0; tk < KSEL; tk++) {
            tidx[b * KSEL + tk] = idx[tk];
            tw[b * KSEL + tk]   = e2[tk] * inv2;
            atomicAdd(&counts[idx[tk]], 1);
        }
    }
}

// ---- dispatch bookkeeping ----
__global__ void reset_kernel(int* __restrict__ counts) {
    if (threadIdx.x < NEXP) counts[threadIdx.x] = 0;
}
__global__ void scan_kernel(const int* __restrict__ counts, int* __restrict__ offsets,
                            int* __restrict__ cursor) {
    if (threadIdx.x == 0) {
        int acc = 0;
        for (int e = 0; e < NEXP; e++) { offsets[e] = acc; cursor[e] = acc; acc += counts[e]; }
        offsets[NEXP] = acc;
    }
}
__global__ void scatter_kernel(const int* __restrict__ tidx, int* __restrict__ cursor,
                               int* __restrict__ rowinfo) {
    int i = blockIdx.x * 256 + threadIdx.x;
    if (i < BTOK * KSEL) {
        int pos = atomicAdd(&cursor[tidx[i]], 1);
        rowinfo[pos] = i;
    }
}

// ---- weighted top-k combine -> fp16 plane ----
__global__ void combine_kernel(const float* __restrict__ h2, const float* __restrict__ tw,
                               __half* __restrict__ ff) {
    int idx = blockIdx.x * 256 + threadIdx.x;
    if (idx < BTOK * HDIM) {
        int b = idx >> 10, h = idx & (HDIM - 1);
        const float* base = h2 + ((size_t)b * KSEL) * HDIM + h;
        const float* w = tw + b * KSEL;
        float v = w[0] * base[0] + w[1] * base[HDIM]
                + w[2] * base[2 * HDIM] + w[3] * base[3 * HDIM];
        ff[idx] = __float2half_rn(v);
    }
}

// ---- final head GEMM [4096,512]x[512,20] ----
__global__ void final_kernel(const float* __restrict__ o1, const float* __restrict__ w2,
                             const float* __restrict__ b2, float* __restrict__ out) {
    int b = blockIdx.x;
    __shared__ float row[512];
    int t = threadIdx.x;
    for (int k = t; k < 512; k += 160) row[k] = o1[(size_t)b * 512 + k];
    __syncthreads();
    int c = t >> 3, sub = t & 7;
    float s = 0.0f;
    for (int k = sub; k < 512; k += 8) s += row[k] * w2[k * NCLS + c];
    s += __shfl_down_sync(0xffffffffu, s, 4);
    s += __shfl_down_sync(0xffffffffu, s, 2);
    s += __shfl_down_sync(0xffffffffu, s, 1);
    if (sub == 0) out[b * NCLS + c] = s + b2[c];
}

// ---- launch ----
extern "C" void kernel_launch(void* const* d_in, const int* in_sizes, int n_in,
                              void* d_out, int out_size) {
    const float* wifi      = (const float*)d_in[0];
    const float* rfid      = (const float*)d_in[1];
    const float* gate_w1   = (const float*)d_in[2];
    const float* gate_b1   = (const float*)d_in[3];
    const float* gate_ln_g = (const float*)d_in[4];
    const float* gate_ln_b = (const float*)d_in[5];
    const float* gate_w2   = (const float*)d_in[6];
    const float* gate_b2   = (const float*)d_in[7];
    const float* exp_w1    = (const float*)d_in[8];
    const float* exp_b1    = (const float*)d_in[9];
    const float* exp_bn1_g = (const float*)d_in[10];
    const float* exp_bn1_b = (const float*)d_in[11];
    const float* exp_bn1_m = (const float*)d_in[12];
    const float* exp_bn1_v = (const float*)d_in[13];
    const float* exp_w2    = (const float*)d_in[14];
    const float* exp_b2    = (const float*)d_in[15];
    const float* exp_bn2_g = (const float*)d_in[16];
    const float* exp_bn2_b = (const float*)d_in[17];
    const float* exp_bn2_m = (const float*)d_in[18];
    const float* exp_bn2_v = (const float*)d_in[19];
    const float* fin_w1    = (const float*)d_in[20];
    const float* fin_b1    = (const float*)d_in[21];
    const float* fin_bn_g  = (const float*)d_in[22];
    const float* fin_bn_b  = (const float*)d_in[23];
    const float* fin_bn_m  = (const float*)d_in[24];
    const float* fin_bn_v  = (const float*)d_in[25];
    const float* fin_w2    = (const float*)d_in[26];
    const float* fin_b2    = (const float*)d_in[27];
    float* out = (float*)d_out;

    float *combined, *g1, *tw, *h2, *o1;
    int *tidx, *counts, *cursor, *offsets, *rowinfo;
    __half *combf, *h1f, *fusedf, *ew1f, *ew2f, *fw1f;
    cudaGetSymbolAddress((void**)&combined, g_combined);
    cudaGetSymbolAddress((void**)&combf,    g_combf);
    cudaGetSymbolAddress((void**)&g1,       g_g1);
    cudaGetSymbolAddress((void**)&tidx,     g_tidx);
    cudaGetSymbolAddress((void**)&tw,       g_tw);
    cudaGetSymbolAddress((void**)&counts,   g_counts);
    cudaGetSymbolAddress((void**)&cursor,   g_cursor);
    cudaGetSymbolAddress((void**)&offsets,  g_offsets);
    cudaGetSymbolAddress((void**)&rowinfo,  g_rowinfo);
    cudaGetSymbolAddress((void**)&h1f,      g_h1f);
    cudaGetSymbolAddress((void**)&h2,       g_h2);
    cudaGetSymbolAddress((void**)&fusedf,   g_fusedf);
    cudaGetSymbolAddress((void**)&o1,       g_o1);
    cudaGetSymbolAddress((void**)&ew1f,     g_ew1f);
    cudaGetSymbolAddress((void**)&ew2f,     g_ew2f);
    cudaGetSymbolAddress((void**)&fw1f,     g_fw1f);

    cudaFuncSetAttribute(w_gemm<true, true, false, true, true>,
                         cudaFuncAttributeMaxDynamicSharedMemorySize, WG_SMEM);
    cudaFuncSetAttribute(w_gemm<true, false, true, true, false>,
                         cudaFuncAttributeMaxDynamicSharedMemorySize, WG_SMEM);
    cudaFuncSetAttribute(w_gemm<false, false, false, true, false>,
                         cudaFuncAttributeMaxDynamicSharedMemorySize, WG_SMEM);

    // weight transpose+convert (pure bandwidth)
    wsplit_kernel<<<dim3(32, 16, NEXP), dim3(32, 8)>>>(exp_w1, ew1f, DIN, HDIM);
    wsplit_kernel<<<dim3(32, 32, NEXP), dim3(32, 8)>>>(exp_w2, ew2f, HDIM, HDIM);
    wsplit_kernel<<<dim3(16, 32, 1),    dim3(32, 8)>>>(fin_w1, fw1f, HDIM, 512);

    // 1. concat (fp32 + fp16 plane)
    concat_kernel<<<(BTOK * DIN + 255) / 256, 256>>>(wifi, rfid, combined, combf);
    // 2. gate GEMM1 (exact fp32)
    gate_gemm<<<dim3(32, 8), 256>>>(combined, gate_w1, g1, gate_b1);
    // 3. LN + GELU
    ln_gelu_kernel<<<BTOK, 256>>>(g1, gate_ln_g, gate_ln_b);
    // 4. gate top-4
    reset_kernel<<<1, 32>>>(counts);
    gate_topk_kernel<<<BTOK, 128>>>(g1, gate_w2, gate_b2, tidx, tw, counts);
    // 5. dispatch
    scan_kernel<<<1, 1>>>(counts, offsets, cursor);
    scatter_kernel<<<(BTOK * KSEL + 255) / 256, 256>>>(tidx, cursor, rowinfo);
    // 6. expert GEMM1 (gather, BN1+GELU, fp16 output)
    w_gemm<true, true, false, true, true><<<dim3(32, 8, NEXP), 256, WG_SMEM>>>(
        combf, ew1f, nullptr, h1f, 0, HDIM, DIN,
        offsets, rowinfo, exp_b1, exp_bn1_g, exp_bn1_b, exp_bn1_m, exp_bn1_v);
    // 7. expert GEMM2 (scatter, BN2+GELU, fp32 output)
    w_gemm<true, false, true, true, false><<<dim3(32, 8, NEXP), 256, WG_SMEM>>>(
        h1f, ew2f, h2, nullptr, 0, HDIM, HDIM,
        offsets, rowinfo, exp_b2, exp_bn2_g, exp_bn2_b, exp_bn2_m, exp_bn2_v);
    // 8. combine -> fp16 plane
    combine_kernel<<<(BTOK * HDIM + 255) / 256, 256>>>(h2, tw, fusedf);
    // 9. final GEMM1 (BN+GELU, fp32 output)
    w_gemm<false, false, false, true, false><<<dim3(32, 4, 1), 256, WG_SMEM>>>(
        fusedf, fw1f, o1, nullptr, BTOK, 512, HDIM,
        nullptr, nullptr, fin_b1, fin_bn_g, fin_bn_b, fin_bn_m, fin_bn_v);
    // 10. head
    final_kernel<<<BTOK, 160>>>(o1, fin_w2, fin_b2, out);
}

// round 12
// speedup vs baseline: 3.2981x; 1.2634x over previous
#include <cuda_runtime.h>
#include <cuda_fp16.h>
#include <math.h>
#include <stdint.h>

#define BTOK 4096
#define DIN  512
#define HDIM 1024
#define NEXP 16
#define KSEL 4
#define NCLS 20
#define EPSN 1e-5f

// ---- device scratch (no allocation allowed) ----
__device__ float  g_combined[BTOK * DIN];       // unused by GEMMs now (kept small path)
__device__ __half g_combh[BTOK * DIN];          // hi plane (GEMM1 A, gate A hi)
__device__ __half g_combl[BTOK * DIN];          // lo plane (gate A lo)
__device__ float  g_g1[BTOK * HDIM];
__device__ int    g_tidx[BTOK * KSEL];
__device__ float  g_tw[BTOK * KSEL];
__device__ int    g_counts[NEXP];
__device__ int    g_cursor[NEXP];
__device__ int    g_offsets[NEXP + 1];
__device__ int    g_rowinfo[BTOK * KSEL];
__device__ __half g_h1f[BTOK * KSEL * HDIM];
__device__ float  g_h2[BTOK * KSEL * HDIM];
__device__ __half g_fusedf[BTOK * HDIM];
__device__ float  g_o1[BTOK * 512];
__device__ __half g_ew1f[NEXP * DIN * HDIM];
__device__ __half g_ew2f[NEXP * HDIM * HDIM];
__device__ __half g_fw1f[HDIM * 512];
__device__ __half g_gw1h[DIN * HDIM];           // gate W1 hi/lo [N,K]
__device__ __half g_gw1l[DIN * HDIM];

__device__ __forceinline__ float gelu_f(float x) {
    return 0.5f * x * (1.0f + erff(x * 0.70710678118654752440f));
}
__device__ __forceinline__ uint32_t smem_u32(const void* p) {
    uint32_t a;
    asm("{ .reg .u64 t; cvta.to.shared.u64 t, %1; cvt.u32.u64 %0, t; }" : "=r"(a) : "l"(p));
    return a;
}
__device__ __forceinline__ uint4 ldm4(uint32_t addr) {
    uint4 r;
    asm volatile("ldmatrix.sync.aligned.m8n8.x4.shared.b16 {%0,%1,%2,%3}, [%4];"
                 : "=r"(r.x), "=r"(r.y), "=r"(r.z), "=r"(r.w) : "r"(addr));
    return r;
}
__device__ __forceinline__ void mma_fp16(float* c, const uint4& a, uint32_t b0, uint32_t b1) {
    asm volatile(
        "mma.sync.aligned.m16n8k16.row.col.f32.f16.f16.f32 "
        "{%0,%1,%2,%3}, {%4,%5,%6,%7}, {%8,%9}, {%0,%1,%2,%3};"
        : "+f"(c[0]), "+f"(c[1]), "+f"(c[2]), "+f"(c[3])
        : "r"(a.x), "r"(a.y), "r"(a.z), "r"(a.w), "r"(b0), "r"(b1));
}
__device__ __forceinline__ uint32_t pkh(__half a, __half b) {
    return (uint32_t)__half_as_ushort(a) | ((uint32_t)__half_as_ushort(b) << 16);
}
__device__ __forceinline__ void split2h(float x, __half& h, __half& l) {
    h = __float2half_rn(x);
    l = __float2half_rn(x - __half2float(h));
}

// ---- concat: fp32 + fp16 hi/lo planes ----
__global__ void concat_kernel(const float* __restrict__ wifi, const float* __restrict__ rfid,
                              float* __restrict__ comb,
                              __half* __restrict__ ch, __half* __restrict__ cl) {
    int i = blockIdx.x * 256 + threadIdx.x;
    if (i < BTOK * DIN) {
        int b = i >> 9, c = i & 511;
        float v = (c < 256) ? wifi[b * 256 + c] : rfid[b * 256 + (c - 256)];
        comb[i] = v;
        __half h, l; split2h(v, h, l);
        ch[i] = h; cl[i] = l;
    }
}

// ---- weight transpose + fp16 convert (1 plane): W[e,K,N] -> T[e,N,K] ----
__global__ void wsplit_kernel(const float* __restrict__ W, __half* __restrict__ Tf,
                              int K, int N) {
    __shared__ float tile[32][33];
    size_t base = (size_t)blockIdx.z * K * N;
    int k0 = blockIdx.y * 32, n0 = blockIdx.x * 32;
    int tx = threadIdx.x, ty = threadIdx.y;
#pragma unroll
    for (int i = 0; i < 32; i += 8)
        tile[ty + i][tx] = W[base + (size_t)(k0 + ty + i) * N + n0 + tx];
    __syncthreads();
#pragma unroll
    for (int i = 0; i < 32; i += 8) {
        int n = n0 + ty + i, k = k0 + tx;
        Tf[base + (size_t)n * K + k] = __float2half_rn(tile[tx][ty + i]);
    }
}

// ---- weight transpose + fp16 hi/lo split (2 planes) ----
__global__ void wsplit2_kernel(const float* __restrict__ W,
                               __half* __restrict__ Th, __half* __restrict__ Tl,
                               int K, int N) {
    __shared__ float tile[32][33];
    int k0 = blockIdx.y * 32, n0 = blockIdx.x * 32;
    int tx = threadIdx.x, ty = threadIdx.y;
#pragma unroll
    for (int i = 0; i < 32; i += 8)
        tile[ty + i][tx] = W[(size_t)(k0 + ty + i) * N + n0 + tx];
    __syncthreads();
#pragma unroll
    for (int i = 0; i < 32; i += 8) {
        int n = n0 + ty + i, k = k0 + tx;
        __half h, l; split2h(tile[tx][ty + i], h, l);
        Th[(size_t)n * K + k] = h;
        Tl[(size_t)n * K + k] = l;
    }
}

// ---------------------------------------------------------------------------
// fp16 1-pass HMMA GEMM (occ 2): C = A @ B, fp32 accumulate.
// ---------------------------------------------------------------------------
static constexpr int WG_SMEM = 2 * 20480;

template<bool SEG, bool GATHER, bool SCATTER, bool BN, bool OUTS>
__global__ void __launch_bounds__(256, 2) w_gemm(
    const __half* __restrict__ Ap, const __half* __restrict__ Bp,
    float* __restrict__ C, __half* __restrict__ Cf,
    int Mfixed, int N, int K,
    const int* __restrict__ offsets, const int* __restrict__ rowinfo,
    const float* __restrict__ bias,
    const float* __restrict__ bng, const float* __restrict__ bnb,
    const float* __restrict__ bnm, const float* __restrict__ bnv)
{
    extern __shared__ __align__(16) char sm[];
    int m0 = 0, M = Mfixed;
    if (SEG) {
        int e = blockIdx.z;
        m0 = offsets[e];
        M  = offsets[e + 1] - m0;
        Bp += (size_t)e * K * N;
        bias += (size_t)e * N;
        if (BN) { bng += (size_t)e * N; bnb += (size_t)e * N;
                  bnm += (size_t)e * N; bnv += (size_t)e * N; }
    }
    const int mtile = blockIdx.x * 128;
    if (mtile >= M) return;
    const int ntile = blockIdx.y * 128;

    const int tid = threadIdx.x, lane = tid & 31, wid = tid >> 5;
    const int warpM = wid & 3, warpN = wid >> 2;
    const uint32_t smBase = smem_u32(sm);

    const int acg = tid & 7;
    const __half* aP[4]; bool aval[4]; uint32_t aDst[4];
#pragma unroll
    for (int i = 0; i < 4; i++) {
        int row = (tid >> 3) + i * 32;
        bool v = (mtile + row) < M;
        aval[i] = v;
        int tok = 0;
        if (v) { int gr = m0 + mtile + row; tok = GATHER ? (rowinfo[gr] >> 2) : gr; }
        aP[i] = Ap + (size_t)tok * K + acg * 4;
        aDst[i] = (uint32_t)(row * 80 + acg * 8);
    }
    const __half* bPtr[2]; uint32_t bDst[2];
#pragma unroll
    for (int i = 0; i < 2; i++) {
        int idx = tid + (i << 8);
        int row = idx >> 2, cg = idx & 3;
        bPtr[i] = Bp + (size_t)(ntile + row) * K + cg * 8;
        bDst[i] = 10240u + (uint32_t)(row * 80 + cg * 16);
    }

    const int qa = lane >> 3, ra = lane & 7;
    const int lrow = ((qa & 1) << 3) + ra;
    const int lcolB = ((qa >> 1) << 3) * 2;
    const uint32_t aFragOff = (uint32_t)((warpM * 32 + lrow) * 80) + lcolB;
    const uint32_t bFragOff = (uint32_t)((warpN * 64 + lrow) * 80) + lcolB + 10240u;

    float acc[2][8][4];
#pragma unroll
    for (int mt = 0; mt < 2; mt++)
#pragma unroll
        for (int nt = 0; nt < 8; nt++)
#pragma unroll
            for (int q = 0; q < 4; q++) acc[mt][nt][q] = 0.0f;

    const int NC = K >> 5;
    const uint2 z2 = make_uint2(0u, 0u);

    {
        char* base = sm;
#pragma unroll
        for (int i = 0; i < 4; i++)
            *(uint2*)(base + aDst[i]) = aval[i] ? *(const uint2*)aP[i] : z2;
#pragma unroll
        for (int i = 0; i < 2; i++)
            *(uint4*)(base + bDst[i]) = *(const uint4*)bPtr[i];
    }
    __syncthreads();

    for (int c = 0; c < NC; c++) {
        uint2 aR[4]; uint4 bR[2];
        const bool pf = (c + 1) < NC;
        if (pf) {
            const int kc = (c + 1) << 5;
#pragma unroll
            for (int i = 0; i < 4; i++)
                aR[i] = aval[i] ? *(const uint2*)(aP[i] + kc) : z2;
#pragma unroll
            for (int i = 0; i < 2; i++)
                bR[i] = *(const uint4*)(bPtr[i] + kc);
        }
        const uint32_t bb = smBase + (uint32_t)(c & 1) * 20480u;
#pragma unroll
        for (int ks = 0; ks < 2; ks++) {
            const uint32_t kso = ks * 32;
            uint4 ah[2];
#pragma unroll
            for (int mt = 0; mt < 2; mt++)
                ah[mt] = ldm4(bb + aFragOff + mt * 1280u + kso);
            uint32_t bf[8][2];
#pragma unroll
            for (int np = 0; np < 4; np++) {
                uint4 h = ldm4(bb + bFragOff + np * 1280u + kso);
                bf[2*np][0] = h.x; bf[2*np][1] = h.z;
                bf[2*np+1][0] = h.y; bf[2*np+1][1] = h.w;
            }
#pragma unroll
            for (int mt = 0; mt < 2; mt++)
#pragma unroll
                for (int nt = 0; nt < 8; nt++)
                    mma_fp16(acc[mt][nt], ah[mt], bf[nt][0], bf[nt][1]);
        }
        if (pf) {
            char* base = sm + ((c + 1) & 1) * 20480;
#pragma unroll
            for (int i = 0; i < 4; i++)
                *(uint2*)(base + aDst[i]) = aR[i];
#pragma unroll
            for (int i = 0; i < 2; i++)
                *(uint4*)(base + bDst[i]) = bR[i];
        }
        __syncthreads();
    }

    const int g = lane >> 2, tt = lane & 3;
#pragma unroll
    for (int mt = 0; mt < 2; mt++) {
#pragma unroll
        for (int half = 0; half < 2; half++) {
            int rl = mtile + warpM * 32 + mt * 16 + half * 8 + g;
            if (rl < M) {
                int gr = m0 + rl;
                int crow = SCATTER ? rowinfo[gr] : gr;
                size_t rowoff = (size_t)crow * N;
#pragma unroll
                for (int nt = 0; nt < 8; nt++) {
                    int cn = ntile + warpN * 64 + nt * 8 + tt * 2;
                    float x0 = acc[mt][nt][half * 2 + 0] + __ldg(bias + cn);
                    float x1 = acc[mt][nt][half * 2 + 1] + __ldg(bias + cn + 1);
                    if (BN) {
                        x0 = gelu_f((x0 - __ldg(bnm + cn)) * rsqrtf(__ldg(bnv + cn) + EPSN)
                                    * __ldg(bng + cn) + __ldg(bnb + cn));
                        x1 = gelu_f((x1 - __ldg(bnm + cn + 1)) * rsqrtf(__ldg(bnv + cn + 1) + EPSN)
                                    * __ldg(bng + cn + 1) + __ldg(bnb + cn + 1));
                    }
                    if (OUTS) {
                        *(uint32_t*)(Cf + rowoff + cn) =
                            pkh(__float2half_rn(x0), __float2half_rn(x1));
                    } else {
                        *(float2*)(C + rowoff + cn) = make_float2(x0, x1);
                    }
                }
            }
        }
    }
}

// ---------------------------------------------------------------------------
// Gate GEMM: fp16 3-pass (AhBh + AlBh + AhBl), near-fp32 accuracy.
// A planes [4096,512]; B planes [1024,512]; C fp32 g1 + bias.
// SMEM/buffer: Ah@0 Al@10240 Bh@20480 Bl@30720 -> 40960; x2 = 81920.
// ---------------------------------------------------------------------------
static constexpr int GG_SMEM = 2 * 40960;

__global__ void __launch_bounds__(256, 1) gate_hmma(
    const __half* __restrict__ Ahp, const __half* __restrict__ Alp,
    const __half* __restrict__ Bhp, const __half* __restrict__ Blp,
    float* __restrict__ C, const float* __restrict__ bias)
{
    extern __shared__ __align__(16) char sm[];
    const int N = HDIM, K = DIN;
    const int mtile = blockIdx.x * 128, ntile = blockIdx.y * 128;
    const int tid = threadIdx.x, lane = tid & 31, wid = tid >> 5;
    const int warpM = wid & 3, warpN = wid >> 2;
    const uint32_t smBase = smem_u32(sm);

    const int acg = tid & 7;
    const __half* aPh[4]; const __half* aPl[4]; uint32_t aDst[4];
#pragma unroll
    for (int i = 0; i < 4; i++) {
        int row = (tid >> 3) + i * 32;
        size_t off = (size_t)(mtile + row) * K + acg * 4;
        aPh[i] = Ahp + off; aPl[i] = Alp + off;
        aDst[i] = (uint32_t)(row * 80 + acg * 8);
    }
    const __half* bPtr[4]; uint32_t bDst[4];
#pragma unroll
    for (int i = 0; i < 4; i++) {
        int idx = tid + (i << 8);
        int plane = idx >> 9, f = idx & 511;
        int row = f >> 2, cg = f & 3;
        bPtr[i] = (plane ? Blp : Bhp) + (size_t)(ntile + row) * K + cg * 8;
        bDst[i] = (plane ? 30720u : 20480u) + (uint32_t)(row * 80 + cg * 16);
    }

    const int qa = lane >> 3, ra = lane & 7;
    const int lrow = ((qa & 1) << 3) + ra;
    const int lcolB = ((qa >> 1) << 3) * 2;
    const uint32_t aFragOff = (uint32_t)((warpM * 32 + lrow) * 80) + lcolB;
    const uint32_t bFragOff = (uint32_t)((warpN * 64 + lrow) * 80) + lcolB + 20480u;

    float acc[2][8][4];
#pragma unroll
    for (int mt = 0; mt < 2; mt++)
#pragma unroll
        for (int nt = 0; nt < 8; nt++)
#pragma unroll
            for (int q = 0; q < 4; q++) acc[mt][nt][q] = 0.0f;

    const int NC = K >> 5;  // 16
    {
        char* base = sm;
#pragma unroll
        for (int i = 0; i < 4; i++) {
            *(uint2*)(base + aDst[i])         = *(const uint2*)aPh[i];
            *(uint2*)(base + 10240 + aDst[i]) = *(const uint2*)aPl[i];
        }
#pragma unroll
        for (int i = 0; i < 4; i++)
            *(uint4*)(base + bDst[i]) = *(const uint4*)bPtr[i];
    }
    __syncthreads();

    for (int c = 0; c < NC; c++) {
        uint2 aRh[4], aRl[4]; uint4 bR[4];
        const bool pf = (c + 1) < NC;
        if (pf) {
            const int kc = (c + 1) << 5;
#pragma unroll
            for (int i = 0; i < 4; i++) {
                aRh[i] = *(const uint2*)(aPh[i] + kc);
                aRl[i] = *(const uint2*)(aPl[i] + kc);
            }
#pragma unroll
            for (int i = 0; i < 4; i++)
                bR[i] = *(const uint4*)(bPtr[i] + kc);
        }
        const uint32_t bb = smBase + (uint32_t)(c & 1) * 40960u;
#pragma unroll
        for (int ks = 0; ks < 2; ks++) {
            const uint32_t kso = ks * 32;
            uint4 ah[2], al[2];
#pragma unroll
            for (int mt = 0; mt < 2; mt++) {
                uint32_t ao = bb + aFragOff + mt * 1280u + kso;
                ah[mt] = ldm4(ao);
                al[mt] = ldm4(ao + 10240u);
            }
            uint32_t bh[8][2], bl[8][2];
#pragma unroll
            for (int np = 0; np < 4; np++) {
                uint32_t bo = bb + bFragOff + np * 1280u + kso;
                uint4 h = ldm4(bo);
                uint4 l = ldm4(bo + 10240u);
                bh[2*np][0] = h.x; bh[2*np][1] = h.z;
                bh[2*np+1][0] = h.y; bh[2*np+1][1] = h.w;
                bl[2*np][0] = l.x; bl[2*np][1] = l.z;
                bl[2*np+1][0] = l.y; bl[2*np+1][1] = l.w;
            }
#pragma unroll
            for (int mt = 0; mt < 2; mt++)
#pragma unroll
                for (int nt = 0; nt < 8; nt++) {
                    mma_fp16(acc[mt][nt], ah[mt], bh[nt][0], bh[nt][1]);
                    mma_fp16(acc[mt][nt], al[mt], bh[nt][0], bh[nt][1]);
                    mma_fp16(acc[mt][nt], ah[mt], bl[nt][0], bl[nt][1]);
                }
        }
        if (pf) {
            char* base = sm + ((c + 1) & 1) * 40960;
#pragma unroll
            for (int i = 0; i < 4; i++) {
                *(uint2*)(base + aDst[i])         = aRh[i];
                *(uint2*)(base + 10240 + aDst[i]) = aRl[i];
            }
#pragma unroll
            for (int i = 0; i < 4; i++)
                *(uint4*)(base + bDst[i]) = bR[i];
        }
        __syncthreads();
    }

    const int g = lane >> 2, tt = lane & 3;
#pragma unroll
    for (int mt = 0; mt < 2; mt++) {
#pragma unroll
        for (int half = 0; half < 2; half++) {
            int rl = mtile + warpM * 32 + mt * 16 + half * 8 + g;
            float* cp = C + (size_t)rl * N;
#pragma unroll
            for (int nt = 0; nt < 8; nt++) {
                int cn = ntile + warpN * 64 + nt * 8 + tt * 2;
                float x0 = acc[mt][nt][half * 2 + 0] + __ldg(bias + cn);
                float x1 = acc[mt][nt][half * 2 + 1] + __ldg(bias + cn + 1);
                *(float2*)(cp + cn) = make_float2(x0, x1);
            }
        }
    }
}

// ---- LayerNorm + GELU (in place, row=1024) ----
__global__ void ln_gelu_kernel(float* __restrict__ x, const float* __restrict__ g,
                               const float* __restrict__ b) {
    int row = blockIdx.x;
    float* xr = x + (size_t)row * HDIM;
    int t = threadIdx.x;
    float4 v = *(float4*)&xr[t * 4];
    float s = v.x + v.y + v.z + v.w;
    float q = v.x * v.x + v.y * v.y + v.z * v.z + v.w * v.w;
#pragma unroll
    for (int o = 16; o; o >>= 1) {
        s += __shfl_down_sync(0xffffffffu, s, o);
        q += __shfl_down_sync(0xffffffffu, q, o);
    }
    __shared__ float ss[8], qq[8];
    int w = t >> 5, l = t & 31;
    if (l == 0) { ss[w] = s; qq[w] = q; }
    __syncthreads();
    if (w == 0) {
        s = (l < 8) ? ss[l] : 0.0f;
        q = (l < 8) ? qq[l] : 0.0f;
#pragma unroll
        for (int o = 4; o; o >>= 1) {
            s += __shfl_down_sync(0xffffffffu, s, o);
            q += __shfl_down_sync(0xffffffffu, q, o);
        }
        if (l == 0) { ss[0] = s; qq[0] = q; }
    }
    __syncthreads();
    float mu  = ss[0] * (1.0f / HDIM);
    float var = qq[0] * (1.0f / HDIM) - mu * mu;
    float r = rsqrtf(var + EPSN);
    float4 gv = *(const float4*)&g[t * 4];
    float4 bv = *(const float4*)&b[t * 4];
    v.x = gelu_f((v.x - mu) * r * gv.x + bv.x);
    v.y = gelu_f((v.y - mu) * r * gv.y + bv.y);
    v.z = gelu_f((v.z - mu) * r * gv.z + bv.z);
    v.w = gelu_f((v.w - mu) * r * gv.w + bv.w);
    *(float4*)&xr[t * 4] = v;
}

// ---- gate logits + softmax + top4 + renorm ----
__global__ void gate_topk_kernel(const float* __restrict__ g1, const float* __restrict__ w2,
                                 const float* __restrict__ b2, int* __restrict__ tidx,
                                 float* __restrict__ tw, int* __restrict__ counts) {
    int b = blockIdx.x, t = threadIdx.x;
    int e = t >> 3, sub = t & 7;
    const float* row = g1 + (size_t)b * HDIM;
    float s = 0.0f;
    for (int k = sub; k < HDIM; k += 8) s += row[k] * w2[k * NEXP + e];
    s += __shfl_down_sync(0xffffffffu, s, 4);
    s += __shfl_down_sync(0xffffffffu, s, 2);
    s += __shfl_down_sync(0xffffffffu, s, 1);
    __shared__ float logit[NEXP];
    if (sub == 0) logit[e] = s + b2[e];
    __syncthreads();
    if (t == 0) {
        float mx = -1e30f;
        for (int i = 0; i < NEXP; i++) mx = fmaxf(mx, logit[i]);
        float p[NEXP], sum = 0.0f;
        for (int i = 0; i < NEXP; i++) { p[i] = expf(logit[i] - mx); sum += p[i]; }
        float inv = 1.0f / sum;
        bool used[NEXP];
        for (int i = 0; i < NEXP; i++) used[i] = false;
        int idx[KSEL]; float val[KSEL];
        for (int tk = 0; tk < KSEL; tk++) {
            int best = -1; float bv = -1e30f;
            for (int i = 0; i < NEXP; i++)
                if (!used[i] && p[i] > bv) { bv = p[i]; best = i; }
            used[best] = true; idx[tk] = best; val[tk] = bv * inv;
        }
        float m2 = val[0], e2[KSEL], s2 = 0.0f;
        for (int tk = 0; tk < KSEL; tk++) { e2[tk] = expf(val[tk] - m2); s2 += e2[tk]; }
        float inv2 = 1.0f / s2;
        for (int tk = 0; tk < KSEL; tk++) {
            tidx[b * KSEL + tk] = idx[tk];
            tw[b * KSEL + tk]   = e2[tk] * inv2;
            atomicAdd(&counts[idx[tk]], 1);
        }
    }
}

// ---- dispatch bookkeeping ----
__global__ void reset_kernel(int* __restrict__ counts) {
    if (threadIdx.x < NEXP) counts[threadIdx.x] = 0;
}
__global__ void scan_kernel(const int* __restrict__ counts, int* __restrict__ offsets,
                            int* __restrict__ cursor) {
    if (threadIdx.x == 0) {
        int acc = 0;
        for (int e = 0; e < NEXP; e++) { offsets[e] = acc; cursor[e] = acc; acc += counts[e]; }
        offsets[NEXP] = acc;
    }
}
__global__ void scatter_kernel(const int* __restrict__ tidx, int* __restrict__ cursor,
                               int* __restrict__ rowinfo) {
    int i = blockIdx.x * 256 + threadIdx.x;
    if (i < BTOK * KSEL) {
        int pos = atomicAdd(&cursor[tidx[i]], 1);
        rowinfo[pos] = i;
    }
}

// ---- weighted top-k combine -> fp16 plane ----
__global__ void combine_kernel(const float* __restrict__ h2, const float* __restrict__ tw,
                               __half* __restrict__ ff) {
    int idx = blockIdx.x * 256 + threadIdx.x;
    if (idx < BTOK * HDIM) {
        int b = idx >> 10, h = idx & (HDIM - 1);
        const float* base = h2 + ((size_t)b * KSEL) * HDIM + h;
        const float* w = tw + b * KSEL;
        float v = w[0] * base[0] + w[1] * base[HDIM]
                + w[2] * base[2 * HDIM] + w[3] * base[3 * HDIM];
        ff[idx] = __float2half_rn(v);
    }
}

// ---- final head GEMM [4096,512]x[512,20] ----
__global__ void final_kernel(const float* __restrict__ o1, const float* __restrict__ w2,
                             const float* __restrict__ b2, float* __restrict__ out) {
    int b = blockIdx.x;
    __shared__ float row[512];
    int t = threadIdx.x;
    for (int k = t; k < 512; k += 160) row[k] = o1[(size_t)b * 512 + k];
    __syncthreads();
    int c = t >> 3, sub = t & 7;
    float s = 0.0f;
    for (int k = sub; k < 512; k += 8) s += row[k] * w2[k * NCLS + c];
    s += __shfl_down_sync(0xffffffffu, s, 4);
    s += __shfl_down_sync(0xffffffffu, s, 2);
    s += __shfl_down_sync(0xffffffffu, s, 1);
    if (sub == 0) out[b * NCLS + c] = s + b2[c];
}

// ---- launch ----
extern "C" void kernel_launch(void* const* d_in, const int* in_sizes, int n_in,
                              void* d_out, int out_size) {
    const float* wifi      = (const float*)d_in[0];
    const float* rfid      = (const float*)d_in[1];
    const float* gate_w1   = (const float*)d_in[2];
    const float* gate_b1   = (const float*)d_in[3];
    const float* gate_ln_g = (const float*)d_in[4];
    const float* gate_ln_b = (const float*)d_in[5];
    const float* gate_w2   = (const float*)d_in[6];
    const float* gate_b2   = (const float*)d_in[7];
    const float* exp_w1    = (const float*)d_in[8];
    const float* exp_b1    = (const float*)d_in[9];
    const float* exp_bn1_g = (const float*)d_in[10];
    const float* exp_bn1_b = (const float*)d_in[11];
    const float* exp_bn1_m = (const float*)d_in[12];
    const float* exp_bn1_v = (const float*)d_in[13];
    const float* exp_w2    = (const float*)d_in[14];
    const float* exp_b2    = (const float*)d_in[15];
    const float* exp_bn2_g = (const float*)d_in[16];
    const float* exp_bn2_b = (const float*)d_in[17];
    const float* exp_bn2_m = (const float*)d_in[18];
    const float* exp_bn2_v = (const float*)d_in[19];
    const float* fin_w1    = (const float*)d_in[20];
    const float* fin_b1    = (const float*)d_in[21];
    const float* fin_bn_g  = (const float*)d_in[22];
    const float* fin_bn_b  = (const float*)d_in[23];
    const float* fin_bn_m  = (const float*)d_in[24];
    const float* fin_bn_v  = (const float*)d_in[25];
    const float* fin_w2    = (const float*)d_in[26];
    const float* fin_b2    = (const float*)d_in[27];
    float* out = (float*)d_out;

    float *combined, *g1, *tw, *h2, *o1;
    int *tidx, *counts, *cursor, *offsets, *rowinfo;
    __half *combh, *combl, *h1f, *fusedf, *ew1f, *ew2f, *fw1f, *gw1h, *gw1l;
    cudaGetSymbolAddress((void**)&combined, g_combined);
    cudaGetSymbolAddress((void**)&combh,    g_combh);
    cudaGetSymbolAddress((void**)&combl,    g_combl);
    cudaGetSymbolAddress((void**)&g1,       g_g1);
    cudaGetSymbolAddress((void**)&tidx,     g_tidx);
    cudaGetSymbolAddress((void**)&tw,       g_tw);
    cudaGetSymbolAddress((void**)&counts,   g_counts);
    cudaGetSymbolAddress((void**)&cursor,   g_cursor);
    cudaGetSymbolAddress((void**)&offsets,  g_offsets);
    cudaGetSymbolAddress((void**)&rowinfo,  g_rowinfo);
    cudaGetSymbolAddress((void**)&h1f,      g_h1f);
    cudaGetSymbolAddress((void**)&h2,       g_h2);
    cudaGetSymbolAddress((void**)&fusedf,   g_fusedf);
    cudaGetSymbolAddress((void**)&o1,       g_o1);
    cudaGetSymbolAddress((void**)&ew1f,     g_ew1f);
    cudaGetSymbolAddress((void**)&ew2f,     g_ew2f);
    cudaGetSymbolAddress((void**)&fw1f,     g_fw1f);
    cudaGetSymbolAddress((void**)&gw1h,     g_gw1h);
    cudaGetSymbolAddress((void**)&gw1l,     g_gw1l);

    cudaFuncSetAttribute(w_gemm<true, true, false, true, true>,
                         cudaFuncAttributeMaxDynamicSharedMemorySize, WG_SMEM);
    cudaFuncSetAttribute(w_gemm<true, false, true, true, false>,
                         cudaFuncAttributeMaxDynamicSharedMemorySize, WG_SMEM);
    cudaFuncSetAttribute(w_gemm<false, false, false, true, false>,
                         cudaFuncAttributeMaxDynamicSharedMemorySize, WG_SMEM);
    cudaFuncSetAttribute(gate_hmma,
                         cudaFuncAttributeMaxDynamicSharedMemorySize, GG_SMEM);

    // weight transpose+convert (pure bandwidth)
    wsplit_kernel<<<dim3(32, 16, NEXP), dim3(32, 8)>>>(exp_w1, ew1f, DIN, HDIM);
    wsplit_kernel<<<dim3(32, 32, NEXP), dim3(32, 8)>>>(exp_w2, ew2f, HDIM, HDIM);
    wsplit_kernel<<<dim3(16, 32, 1),    dim3(32, 8)>>>(fin_w1, fw1f, HDIM, 512);
    wsplit2_kernel<<<dim3(32, 16), dim3(32, 8)>>>(gate_w1, gw1h, gw1l, DIN, HDIM);

    // 1. concat (fp32 + fp16 hi/lo planes)
    concat_kernel<<<(BTOK * DIN + 255) / 256, 256>>>(wifi, rfid, combined, combh, combl);
    // 2. gate GEMM1 (fp16 3-pass, near-fp32)
    gate_hmma<<<dim3(32, 8), 256, GG_SMEM>>>(combh, combl, gw1h, gw1l, g1, gate_b1);
    // 3. LN + GELU
    ln_gelu_kernel<<<BTOK, 256>>>(g1, gate_ln_g, gate_ln_b);
    // 4. gate top-4
    reset_kernel<<<1, 32>>>(counts);
    gate_topk_kernel<<<BTOK, 128>>>(g1, gate_w2, gate_b2, tidx, tw, counts);
    // 5. dispatch
    scan_kernel<<<1, 1>>>(counts, offsets, cursor);
    scatter_kernel<<<(BTOK * KSEL + 255) / 256, 256>>>(tidx, cursor, rowinfo);
    // 6. expert GEMM1 (gather, BN1+GELU, fp16 output)
    w_gemm<true, true, false, true, true><<<dim3(32, 8, NEXP), 256, WG_SMEM>>>(
        combh, ew1f, nullptr, h1f, 0, HDIM, DIN,
        offsets, rowinfo, exp_b1, exp_bn1_g, exp_bn1_b, exp_bn1_m, exp_bn1_v);
    // 7. expert GEMM2 (scatter, BN2+GELU, fp32 output)
    w_gemm<true, false, true, true, false><<<dim3(32, 8, NEXP), 256, WG_SMEM>>>(
        h1f, ew2f, h2, nullptr, 0, HDIM, HDIM,
        offsets, rowinfo, exp_b2, exp_bn2_g, exp_bn2_b, exp_bn2_m, exp_bn2_v);
    // 8. combine -> fp16 plane
    combine_kernel<<<(BTOK * HDIM + 255) / 256, 256>>>(h2, tw, fusedf);
    // 9. final GEMM1 (BN+GELU, fp32 output)
    w_gemm<false, false, false, true, false><<<dim3(32, 4, 1), 256, WG_SMEM>>>(
        fusedf, fw1f, o1, nullptr, BTOK, 512, HDIM,
        nullptr, nullptr, fin_b1, fin_bn_g, fin_bn_b, fin_bn_m, fin_bn_v);
    // 10. head
    final_kernel<<<BTOK, 160>>>(o1, fin_w2, fin_b2, out);
}